// round 8
// baseline (speedup 1.0000x reference)
#include <cuda_runtime.h>
#include <cuda_bf16.h>

// ---------------- problem constants ----------------
#define BB   4
#define TT   16
#define NN   1000
#define FIN  8
#define EE   8000
#define EP   9000          // edges + self loops
#define HID  64
#define HEADS 4
#define LL   5
#define GG   64            // B*T graphs
#define RR   64000         // G*N rows
#define NH   64000         // N*HID
#define GATES 192
#define KCH  512
#define NCHUNK 125

#define AGG4_SMEM (NN * 16 * 4)   // 64000 B

// H layout: slice-major. Column c of row r lives at
//   g_H[(c>>4) * (RR*16) + r*16 + (c&15)]
#define HSLICE (RR * 16)

// ---------------- device scratch ----------------
__device__ float g_X0[RR * HID];
__device__ float g_X1[RR * HID];
__device__ float g_H [16 * HSLICE];
__device__ float g_ls[RR * HEADS];
__device__ float g_ld[RR * HEADS];
__device__ int   g_off[NN + 1];
__device__ int   g_srcList[EP];
__device__ int   g_eid[EP];
__device__ float2 g_ew[GG * HEADS * EP];     // (expWeight, srcBits=src*16) per edge
__device__ float g_snorm[GG * HEADS * NN];   // 1/sum per (g,h,node)
__device__ float g_GIpart[NCHUNK * GG * GATES];
__device__ float g_GI[GG * GATES];
__device__ float g_hT[BB * HID];

// ---------------- fused pre-kernel: CSR build (block 4000) + input proj ------
__global__ void __launch_bounds__(1024) k_pre(const int* __restrict__ edge_index,
                                              const float* __restrict__ x,
                                              const float* __restrict__ W_in,
                                              const float* __restrict__ b_in) {
    int tid = threadIdx.x;
    if (blockIdx.x < 4000) {
        // input projection: 16 rows x 64 channels per block
        int r = blockIdx.x * 16 + (tid >> 6);
        int c = tid & 63;
        float s = b_in[c];
#pragma unroll
        for (int f = 0; f < FIN; f++)
            s += x[r * FIN + f] * W_in[f * HID + c];
        g_X0[r * HID + c] = s;
        return;
    }
    // ---- CSR build (deterministic), one block ----
    __shared__ int scnt[1024];
    __shared__ int sscan[1024];
    __shared__ int scur[1024];
    scnt[tid] = 0;
    __syncthreads();
    for (int e = tid; e < EE; e += 1024)
        atomicAdd(&scnt[edge_index[EE + e]], 1);
    __syncthreads();
    int v = (tid < NN) ? (scnt[tid] + 1) : 0;    // +1 self loop
    sscan[tid] = v;
    __syncthreads();
    for (int o = 1; o < 1024; o <<= 1) {
        int add = (tid >= o) ? sscan[tid - o] : 0;
        __syncthreads();
        sscan[tid] += add;
        __syncthreads();
    }
    if (tid < NN) {
        g_off[tid + 1] = sscan[tid];
        scur[tid] = (tid == 0) ? 0 : sscan[tid - 1];
    }
    if (tid == 0) g_off[0] = 0;
    __syncthreads();
    for (int e = tid; e < EP; e += 1024) {
        int s, d;
        if (e < EE) { s = edge_index[e]; d = edge_index[EE + e]; }
        else        { s = e - EE;        d = e - EE; }
        int pos = atomicAdd(&scur[d], 1);
        g_srcList[pos] = s;
        g_eid[pos] = e;
    }
    __syncthreads();
    if (tid < NN) {                       // stable order by edge id
        int s0 = g_off[tid], s1 = g_off[tid + 1];
        for (int i = s0 + 1; i < s1; i++) {
            int id = g_eid[i], sv = g_srcList[i];
            int j = i - 1;
            while (j >= s0 && g_eid[j] > id) {
                g_eid[j + 1] = g_eid[j];
                g_srcList[j + 1] = g_srcList[j];
                j--;
            }
            g_eid[j + 1] = id;
            g_srcList[j + 1] = sv;
        }
    }
}

// ---------------- GAT GEMM + fused ls/ld epilogue ----------------------------
__global__ void __launch_bounds__(256) k_gat_gemm(int inBuf, const float* __restrict__ W,
                                                  const float* __restrict__ asrc,
                                                  const float* __restrict__ adst) {
    __shared__ float sm[12288];                 // 48KB, aliased
    float (*As)[64]  = (float(*)[64])sm;        // [64][64]
    float (*Ws)[256] = (float(*)[256])(sm + 4096); // [32][256]
    const float* __restrict__ X = inBuf ? g_X1 : g_X0;
    int rowBase = blockIdx.x * 64;
    int tid = threadIdx.x;

    const float4* X4 = (const float4*)(X + (size_t)rowBase * 64);
#pragma unroll
    for (int q = 0; q < 4; q++) {
        int idx = tid + q * 256;
        int r = idx & 63, k4 = idx >> 6;
        float4 v = X4[r * 16 + k4];
        As[k4 * 4 + 0][r] = v.x;
        As[k4 * 4 + 1][r] = v.y;
        As[k4 * 4 + 2][r] = v.z;
        As[k4 * 4 + 3][r] = v.w;
    }

    int lane = tid & 31, w = tid >> 5;
    int ry2 = lane >> 2, cx2 = lane & 3;
    int cg = w * 4 + cx2;                       // 0..31
    float acc[8][8] = {};
    const float4* W4 = (const float4*)W;

#pragma unroll
    for (int half = 0; half < 2; half++) {
        __syncthreads();
#pragma unroll
        for (int q = 0; q < 8; q++) {
            int idx = tid + q * 256;
            ((float4*)Ws)[idx] = W4[half * 2048 + idx];
        }
        __syncthreads();
#pragma unroll
        for (int kk = 0; kk < 32; kk++) {
            int k = half * 32 + kk;
            float4 a0 = *(const float4*)&As[k][ry2 * 4];
            float4 a1 = *(const float4*)&As[k][32 + ry2 * 4];
            float4 b0 = *(const float4*)&Ws[kk][cg * 4];
            float4 b1 = *(const float4*)&Ws[kk][128 + cg * 4];
            float av[8] = {a0.x, a0.y, a0.z, a0.w, a1.x, a1.y, a1.z, a1.w};
            float bv[8] = {b0.x, b0.y, b0.z, b0.w, b1.x, b1.y, b1.z, b1.w};
#pragma unroll
            for (int i = 0; i < 8; i++)
#pragma unroll
                for (int j = 0; j < 8; j++)
                    acc[i][j] += av[i] * bv[j];
        }
    }
    // store H in slice-major layout
    {
        int slLo = cg >> 2, slHi = 8 + (cg >> 2);
        int chB = (cg & 3) * 4;
#pragma unroll
        for (int i = 0; i < 8; i++) {
            int r = rowBase + ((i < 4) ? (ry2 * 4 + i) : (32 + ry2 * 4 + (i - 4)));
            *(float4*)&g_H[(size_t)slLo * HSLICE + r * 16 + chB] =
                make_float4(acc[i][0], acc[i][1], acc[i][2], acc[i][3]);
            *(float4*)&g_H[(size_t)slHi * HSLICE + r * 16 + chB] =
                make_float4(acc[i][4], acc[i][5], acc[i][6], acc[i][7]);
        }
    }

    // ---- fused ls/ld epilogue ----
    __syncthreads();                            // done reading As/Ws
    float (*redls)[4][16] = (float(*)[4][16])sm;          // [64][4][16]
    float (*redld)[4][16] = (float(*)[4][16])(sm + 4096);
    float as_lo[4], as_hi[4], ad_lo[4], ad_hi[4];
#pragma unroll
    for (int j = 0; j < 4; j++) {
        as_lo[j] = asrc[cg * 4 + j];
        as_hi[j] = asrc[128 + cg * 4 + j];
        ad_lo[j] = adst[cg * 4 + j];
        ad_hi[j] = adst[128 + cg * 4 + j];
    }
    int hA = cg >> 4;                           // head of low half (0/1)
    int slot = (w & 3) * 4 + cx2;               // 0..15
#pragma unroll
    for (int i = 0; i < 8; i++) {
        int r = (i < 4) ? (ry2 * 4 + i) : (32 + ry2 * 4 + (i - 4));
        float pls0 = 0, pls1 = 0, pld0 = 0, pld1 = 0;
#pragma unroll
        for (int j = 0; j < 4; j++) {
            pls0 += acc[i][j] * as_lo[j];
            pls1 += acc[i][4 + j] * as_hi[j];
            pld0 += acc[i][j] * ad_lo[j];
            pld1 += acc[i][4 + j] * ad_hi[j];
        }
        redls[r][hA][slot] = pls0;
        redls[r][2 + hA][slot] = pls1;
        redld[r][hA][slot] = pld0;
        redld[r][2 + hA][slot] = pld1;
    }
    __syncthreads();
    {
        int r = tid >> 2, h = tid & 3;
        float s = 0, d = 0;
#pragma unroll
        for (int k = 0; k < 16; k++) { s += redls[r][h][k]; d += redld[r][h][k]; }
        g_ls[(rowBase + r) * 4 + h] = s;
        g_ld[(rowBase + r) * 4 + h] = d;
    }
}

// ---------------- softmax edge records, all 4 heads per graph ----------------
// grid GG; 512 threads; thread-per-node; ls/ld staged in smem.
// Writes g_ew[(g,h)][j] = (expWeight, srcBits=src*16), g_snorm[(g,h)][n] = 1/sum.
__global__ void __launch_bounds__(512) k_weights2() {
    __shared__ float sls[HEADS][1024];
    __shared__ float sld[HEADS][1024];
    int g = blockIdx.x;
    size_t gb = (size_t)g * NN;
    int tid = threadIdx.x;
    const float* __restrict__ lsrc = g_ls + gb * HEADS;
    const float* __restrict__ ldsr = g_ld + gb * HEADS;
    for (int i = tid; i < NN * HEADS; i += 512) {
        int n = i >> 2, h = i & 3;
        sls[h][n] = lsrc[i];
        sld[h][n] = ldsr[i];
    }
    __syncthreads();

    float2* __restrict__ ew0 = g_ew + (size_t)(g * HEADS + 0) * EP;
    float2* __restrict__ ew1 = g_ew + (size_t)(g * HEADS + 1) * EP;
    float2* __restrict__ ew2 = g_ew + (size_t)(g * HEADS + 2) * EP;
    float2* __restrict__ ew3 = g_ew + (size_t)(g * HEADS + 3) * EP;

    for (int n = tid; n < NN; n += 512) {
        int s0 = g_off[n], s1 = g_off[n + 1];
        float ld0 = sld[0][n], ld1 = sld[1][n], ld2 = sld[2][n], ld3 = sld[3][n];
        float sm0 = 0.f, sm1 = 0.f, sm2 = 0.f, sm3 = 0.f;
        for (int j = s0; j < s1; j++) {
            int s = g_srcList[j];
            float sb = __int_as_float(s * 16);          // pre-scaled row offset
            float v0 = sls[0][s] + ld0; v0 = v0 > 0.f ? v0 : 0.2f * v0;
            float v1 = sls[1][s] + ld1; v1 = v1 > 0.f ? v1 : 0.2f * v1;
            float v2 = sls[2][s] + ld2; v2 = v2 > 0.f ? v2 : 0.2f * v2;
            float v3 = sls[3][s] + ld3; v3 = v3 > 0.f ? v3 : 0.2f * v3;
            float w0 = __expf(v0), w1 = __expf(v1), w2 = __expf(v2), w3 = __expf(v3);
            ew0[j] = make_float2(w0, sb);
            ew1[j] = make_float2(w1, sb);
            ew2[j] = make_float2(w2, sb);
            ew3[j] = make_float2(w3, sb);
            sm0 += w0; sm1 += w1; sm2 += w2; sm3 += w3;
        }
        g_snorm[(size_t)(g * HEADS + 0) * NN + n] = 1.f / (sm0 + 1e-16f);
        g_snorm[(size_t)(g * HEADS + 1) * NN + n] = 1.f / (sm1 + 1e-16f);
        g_snorm[(size_t)(g * HEADS + 2) * NN + n] = 1.f / (sm2 + 1e-16f);
        g_snorm[(size_t)(g * HEADS + 3) * NN + n] = 1.f / (sm3 + 1e-16f);
    }
}

// ---------------- GAT aggregate v6: full warp per node, 2 edges/iter ---------
// grid (GG, 16): slice sl, head h = sl>>2. 512 threads = 16 warps.
// Lanes 0-15 handle even edge indices, lanes 16-31 odd — same loop bounds,
// no divergence. srcBits in ew.y is pre-scaled (src*16).
__global__ void __launch_bounds__(512) k_gat_agg4() {
    extern __shared__ float Hs[];               // [1000][16]
    int g = blockIdx.x, sl = blockIdx.y;
    int h = sl >> 2;
    int tid = threadIdx.x;
    int lane = tid & 31, w = tid >> 5;
    int hi = lane >> 4, ch = lane & 15;
    size_t gb = (size_t)g * NN;
    float* __restrict__ Hsl = g_H + (size_t)sl * HSLICE + gb * 16;

    // Phase A: fully coalesced contiguous 64KB copy
    const float4* src4 = (const float4*)Hsl;
    for (int idx = tid; idx < NN * 4; idx += 512)
        ((float4*)Hs)[idx] = src4[idx];
    __syncthreads();

    const float2* __restrict__ ew = g_ew + (size_t)(g * HEADS + h) * EP;
    const float* __restrict__ nrm = g_snorm + (size_t)(g * HEADS + h) * NN;

    // Phase B: warp per node; this lane covers edges s0+hi, s0+hi+2, ...
    for (int n = w; n < NN; n += 16) {
        int s0 = g_off[n], s1 = g_off[n + 1];
        float acc = 0.f;
        int j = s0 + hi;
        for (; j + 2 < s1; j += 4) {            // 2 edges per half in flight
            float2 e0 = ew[j];
            float2 e1 = ew[j + 2];
            acc += e0.x * Hs[__float_as_int(e0.y) + ch];
            acc += e1.x * Hs[__float_as_int(e1.y) + ch];
        }
        if (j < s1) {
            float2 e0 = ew[j];
            acc += e0.x * Hs[__float_as_int(e0.y) + ch];
        }
        acc += __shfl_down_sync(0xffffffffu, acc, 16);
        if (hi == 0)
            Hsl[n * 16 + ch] = acc * nrm[n];    // in-place, 64B coalesced
    }
}

// ---------------- head mean + bias + elu -> X ----------------
__global__ void k_finish(const float* __restrict__ bg_l, int outBuf) {
    float* __restrict__ Xout = outBuf ? g_X1 : g_X0;
    int tid = threadIdx.x;
    int r = blockIdx.x * 4 + (tid >> 6);
    int c = tid & 63;
    float v = 0.f;
#pragma unroll
    for (int h = 0; h < HEADS; h++) {
        int cc = h * 64 + c;
        v += g_H[(size_t)(cc >> 4) * HSLICE + (size_t)r * 16 + (cc & 15)];
    }
    v = 0.25f * v + bg_l[c];
    v = v > 0.f ? v : expm1f(v);
    Xout[(size_t)r * 64 + c] = v;
}

// ---------------- GI split-K GEMM (transposed smem, float4 frags) ------------
__global__ void __launch_bounds__(256) k_gi_gemm(const float* __restrict__ Wih) {
    __shared__ float As[32][68];
    __shared__ float Ws[32][68];
    int kBase = blockIdx.x * KCH;
    int gateBase = blockIdx.y * 64;
    int tid = threadIdx.x;
    int tx = tid & 15, ty = tid >> 4;
    float acc[4][4] = {};
    for (int kt = 0; kt < KCH / 32; kt++) {
        int k0 = kBase + kt * 32;
        __syncthreads();
#pragma unroll
        for (int i = 0; i < 8; i++) {
            int idx = tid + i * 256;
            int r = idx >> 5, kk = idx & 31;
            As[kk][r] = g_X1[r * NH + k0 + kk];
            Ws[kk][r] = Wih[(size_t)(gateBase + r) * NH + k0 + kk];
        }
        __syncthreads();
#pragma unroll
        for (int kk = 0; kk < 32; kk++) {
            float4 a = *(const float4*)&As[kk][ty * 4];
            float4 wv = *(const float4*)&Ws[kk][tx * 4];
            float av[4] = {a.x, a.y, a.z, a.w};
            float bw[4] = {wv.x, wv.y, wv.z, wv.w};
#pragma unroll
            for (int i = 0; i < 4; i++)
#pragma unroll
                for (int j = 0; j < 4; j++)
                    acc[i][j] += av[i] * bw[j];
        }
    }
#pragma unroll
    for (int i = 0; i < 4; i++)
#pragma unroll
        for (int j = 0; j < 4; j++)
            g_GIpart[(blockIdx.x * GG + ty * 4 + i) * GATES + gateBase + tx * 4 + j] = acc[i][j];
}

__global__ void k_gi_reduce(const float* __restrict__ b_ih) {
    int idx = blockIdx.x * blockDim.x + threadIdx.x;
    int j = idx % GATES;
    float s = b_ih[j];
    for (int kc = 0; kc < NCHUNK; kc++)
        s += g_GIpart[kc * GG * GATES + idx];
    g_GI[idx] = s;
}

// ---------------- GRU recurrence ----------------
__global__ void __launch_bounds__(256) k_gru(const float* __restrict__ Whh,
                                             const float* __restrict__ bhh) {
    __shared__ float h[BB][HID];
    __shared__ float gh[BB][GATES];
    int tid = threadIdx.x;
    h[tid >> 6][tid & 63] = 0.f;
    __syncthreads();
    for (int t = 0; t < TT; t++) {
#pragma unroll
        for (int q = 0; q < 3; q++) {
            int idx = tid + q * 256;
            int b = idx / GATES, j = idx % GATES;
            float s = bhh[j];
#pragma unroll
            for (int c = 0; c < HID; c++)
                s += h[b][c] * Whh[j * HID + c];
            gh[b][j] = s;
        }
        __syncthreads();
        int b = tid >> 6, c = tid & 63;
        int g = b * TT + t;
        float ir = g_GI[g * GATES + c]        + gh[b][c];
        float iz = g_GI[g * GATES + 64 + c]   + gh[b][64 + c];
        float in = g_GI[g * GATES + 128 + c];
        float hn = gh[b][128 + c];
        float r = 1.f / (1.f + expf(-ir));
        float z = 1.f / (1.f + expf(-iz));
        float nn = tanhf(in + r * hn);
        float hnew = (1.f - z) * nn + z * h[b][c];
        __syncthreads();
        h[b][c] = hnew;
        __syncthreads();
    }
    g_hT[tid] = h[tid >> 6][tid & 63];
}

// ---------------- final FC ----------------
__global__ void k_fc(const float* __restrict__ Wfc, const float* __restrict__ bfc,
                     float* __restrict__ out) {
    int b = blockIdx.x;
    int n = blockIdx.y * 256 + threadIdx.x;
    if (n >= NN) return;
    float s = bfc[n];
#pragma unroll
    for (int c = 0; c < HID; c++)
        s += g_hT[b * HID + c] * Wfc[c * NN + n];
    out[b * NN + n] = s;
}

// ---------------- launcher ----------------
extern "C" void kernel_launch(void* const* d_in, const int* in_sizes, int n_in,
                              void* d_out, int out_size) {
    const float* x_seq = (const float*)d_in[0];
    const int*   edge_index = (const int*)d_in[1];
    const float* W_in = (const float*)d_in[3];
    const float* b_in = (const float*)d_in[4];
    const float* Wg   = (const float*)d_in[5];
    const float* a_src= (const float*)d_in[6];
    const float* a_dst= (const float*)d_in[7];
    const float* bg   = (const float*)d_in[8];
    const float* W_ih = (const float*)d_in[9];
    const float* W_hh = (const float*)d_in[10];
    const float* b_ih = (const float*)d_in[11];
    const float* b_hh = (const float*)d_in[12];
    const float* W_fc = (const float*)d_in[13];
    const float* b_fc = (const float*)d_in[14];
    float* out = (float*)d_out;

    cudaFuncSetAttribute(k_gat_agg4,
                         cudaFuncAttributeMaxDynamicSharedMemorySize, AGG4_SMEM);

    // launch 1: fused CSR + input projection
    k_pre<<<4001, 1024>>>(edge_index, x_seq, W_in, b_in);

    // launches 2-4: gemm, weights2, agg4 (#4 = ncu slot -> agg4)
    for (int l = 0; l < LL; l++) {
        int inBuf = l & 1;
        int outBuf = 1 - inBuf;
        k_gat_gemm<<<RR / 64, 256>>>(inBuf, Wg + (size_t)l * HID * 256,
                                     a_src + (size_t)l * HEADS * HID,
                                     a_dst + (size_t)l * HEADS * HID);
        k_weights2<<<GG, 512>>>();
        k_gat_agg4<<<dim3(GG, 16), 512, AGG4_SMEM>>>();
        k_finish<<<RR / 4, 256>>>(bg + (size_t)l * HID, outBuf);
    }
    // final features in g_X1

    k_gi_gemm<<<dim3(NCHUNK, 3), 256>>>(W_ih);
    k_gi_reduce<<<(GG * GATES) / 256, 256>>>(b_ih);
    k_gru<<<1, 256>>>(W_hh, b_hh);
    k_fc<<<dim3(BB, 4), 256>>>(W_fc, b_fc, out);
}

// round 9
// speedup vs baseline: 1.0371x; 1.0371x over previous
#include <cuda_runtime.h>
#include <cuda_bf16.h>

// ---------------- problem constants ----------------
#define BB   4
#define TT   16
#define NN   1000
#define FIN  8
#define EE   8000
#define EP   9000          // edges + self loops
#define HID  64
#define HEADS 4
#define LL   5
#define GG   64            // B*T graphs
#define RR   64000         // G*N rows
#define NH   64000         // N*HID
#define GATES 192
#define KCH  512
#define NCHUNK 125

#define AGG4_SMEM (NN * 16 * 4)   // 64000 B

// H layout: slice-major. Column c of row r lives at
//   g_H[(c>>4) * (RR*16) + r*16 + (c&15)]
#define HSLICE (RR * 16)

// ---------------- device scratch ----------------
__device__ float g_X0[RR * HID];
__device__ float g_X1[RR * HID];
__device__ float g_H [16 * HSLICE];
__device__ float g_ls[RR * HEADS];
__device__ float g_ld[RR * HEADS];
__device__ int   g_off[NN + 1];
__device__ int   g_srcList[EP];
__device__ int   g_eid[EP];
__device__ float g_alpha[GG * HEADS * EP];   // NORMALIZED softmax weights
__device__ float g_GIpart[NCHUNK * GG * GATES];
__device__ float g_GI[GG * GATES];
__device__ float g_hT[BB * HID];

// ---------------- CSR build: ONE kernel, one block (deterministic) -----------
__global__ void __launch_bounds__(1024) k_csr_all(const int* __restrict__ edge_index) {
    __shared__ int scnt[1024];
    __shared__ int sscan[1024];
    __shared__ int scur[1024];
    int tid = threadIdx.x;
    scnt[tid] = 0;
    __syncthreads();
    for (int e = tid; e < EE; e += 1024)
        atomicAdd(&scnt[edge_index[EE + e]], 1);
    __syncthreads();
    int v = (tid < NN) ? (scnt[tid] + 1) : 0;    // +1 self loop
    sscan[tid] = v;
    __syncthreads();
    for (int o = 1; o < 1024; o <<= 1) {
        int add = (tid >= o) ? sscan[tid - o] : 0;
        __syncthreads();
        sscan[tid] += add;
        __syncthreads();
    }
    if (tid < NN) {
        g_off[tid + 1] = sscan[tid];
        scur[tid] = (tid == 0) ? 0 : sscan[tid - 1];
    }
    if (tid == 0) g_off[0] = 0;
    __syncthreads();
    for (int e = tid; e < EP; e += 1024) {
        int s, d;
        if (e < EE) { s = edge_index[e]; d = edge_index[EE + e]; }
        else        { s = e - EE;        d = e - EE; }
        int pos = atomicAdd(&scur[d], 1);
        g_srcList[pos] = s;
        g_eid[pos] = e;
    }
    __syncthreads();
    if (tid < NN) {                       // stable order by edge id
        int s0 = g_off[tid], s1 = g_off[tid + 1];
        for (int i = s0 + 1; i < s1; i++) {
            int id = g_eid[i], sv = g_srcList[i];
            int j = i - 1;
            while (j >= s0 && g_eid[j] > id) {
                g_eid[j + 1] = g_eid[j];
                g_srcList[j + 1] = g_srcList[j];
                j--;
            }
            g_eid[j + 1] = id;
            g_srcList[j + 1] = sv;
        }
    }
}

// ---------------- input projection ----------------
__global__ void k_input_fc(const float* __restrict__ x,
                           const float* __restrict__ W_in,
                           const float* __restrict__ b_in) {
    int tid = threadIdx.x;
    int r = blockIdx.x * 4 + (tid >> 6);
    int c = tid & 63;
    float s = b_in[c];
#pragma unroll
    for (int f = 0; f < FIN; f++)
        s += x[r * FIN + f] * W_in[f * HID + c];
    g_X0[r * HID + c] = s;
}

// ---------------- GAT GEMM + fused ls/ld epilogue ----------------------------
// bgPrev == nullptr: As from g_X0 (layer 0).
// else: As[k][r] = elu(0.25 * sum_h H_agg[r][h*64+k] + bgPrev[k])  (fused finish)
// Safe in-place: this block only reads/writes rows rowBase..rowBase+63 of g_H,
// and all reads complete before the first __syncthreads(), before any H store.
__global__ void __launch_bounds__(256) k_gat_gemm(const float* __restrict__ bgPrev,
                                                  const float* __restrict__ W,
                                                  const float* __restrict__ asrc,
                                                  const float* __restrict__ adst) {
    __shared__ float sm[12288];                 // 48KB, aliased
    float (*As)[64]  = (float(*)[64])sm;        // [64][64]
    float (*Ws)[256] = (float(*)[256])(sm + 4096); // [32][256]
    int rowBase = blockIdx.x * 64;
    int tid = threadIdx.x;

    if (bgPrev == nullptr) {
        const float4* X4 = (const float4*)(g_X0 + (size_t)rowBase * 64);
#pragma unroll
        for (int q = 0; q < 4; q++) {
            int idx = tid + q * 256;
            int r = idx & 63, k4 = idx >> 6;
            float4 v = X4[r * 16 + k4];
            As[k4 * 4 + 0][r] = v.x;
            As[k4 * 4 + 1][r] = v.y;
            As[k4 * 4 + 2][r] = v.z;
            As[k4 * 4 + 3][r] = v.w;
        }
    } else {
#pragma unroll
        for (int q = 0; q < 4; q++) {
            int idx = tid + q * 256;
            int r = idx & 63, c = (idx >> 6) * 4;    // c in {0,4,...,60}
            size_t rg = (size_t)(rowBase + r) * 16 + (c & 15);
            float4 v = make_float4(0.f, 0.f, 0.f, 0.f);
#pragma unroll
            for (int h = 0; h < HEADS; h++) {
                float4 t = *(const float4*)&g_H[(size_t)(h * 4 + (c >> 4)) * HSLICE + rg];
                v.x += t.x; v.y += t.y; v.z += t.z; v.w += t.w;
            }
            float e0 = 0.25f * v.x + bgPrev[c];
            float e1 = 0.25f * v.y + bgPrev[c + 1];
            float e2 = 0.25f * v.z + bgPrev[c + 2];
            float e3 = 0.25f * v.w + bgPrev[c + 3];
            As[c + 0][r] = e0 > 0.f ? e0 : expm1f(e0);
            As[c + 1][r] = e1 > 0.f ? e1 : expm1f(e1);
            As[c + 2][r] = e2 > 0.f ? e2 : expm1f(e2);
            As[c + 3][r] = e3 > 0.f ? e3 : expm1f(e3);
        }
    }

    int lane = tid & 31, w = tid >> 5;
    int ry2 = lane >> 2, cx2 = lane & 3;
    int cg = w * 4 + cx2;                       // 0..31
    float acc[8][8] = {};
    const float4* W4 = (const float4*)W;

#pragma unroll
    for (int half = 0; half < 2; half++) {
        __syncthreads();
#pragma unroll
        for (int q = 0; q < 8; q++) {
            int idx = tid + q * 256;
            ((float4*)Ws)[idx] = W4[half * 2048 + idx];
        }
        __syncthreads();
#pragma unroll
        for (int kk = 0; kk < 32; kk++) {
            int k = half * 32 + kk;
            float4 a0 = *(const float4*)&As[k][ry2 * 4];
            float4 a1 = *(const float4*)&As[k][32 + ry2 * 4];
            float4 b0 = *(const float4*)&Ws[kk][cg * 4];
            float4 b1 = *(const float4*)&Ws[kk][128 + cg * 4];
            float av[8] = {a0.x, a0.y, a0.z, a0.w, a1.x, a1.y, a1.z, a1.w};
            float bv[8] = {b0.x, b0.y, b0.z, b0.w, b1.x, b1.y, b1.z, b1.w};
#pragma unroll
            for (int i = 0; i < 8; i++)
#pragma unroll
                for (int j = 0; j < 8; j++)
                    acc[i][j] += av[i] * bv[j];
        }
    }
    // store H in slice-major layout
    {
        int slLo = cg >> 2, slHi = 8 + (cg >> 2);
        int chB = (cg & 3) * 4;
#pragma unroll
        for (int i = 0; i < 8; i++) {
            int r = rowBase + ((i < 4) ? (ry2 * 4 + i) : (32 + ry2 * 4 + (i - 4)));
            *(float4*)&g_H[(size_t)slLo * HSLICE + r * 16 + chB] =
                make_float4(acc[i][0], acc[i][1], acc[i][2], acc[i][3]);
            *(float4*)&g_H[(size_t)slHi * HSLICE + r * 16 + chB] =
                make_float4(acc[i][4], acc[i][5], acc[i][6], acc[i][7]);
        }
    }

    // ---- fused ls/ld epilogue ----
    __syncthreads();                            // done reading As/Ws
    float (*redls)[4][16] = (float(*)[4][16])sm;          // [64][4][16]
    float (*redld)[4][16] = (float(*)[4][16])(sm + 4096);
    float as_lo[4], as_hi[4], ad_lo[4], ad_hi[4];
#pragma unroll
    for (int j = 0; j < 4; j++) {
        as_lo[j] = asrc[cg * 4 + j];
        as_hi[j] = asrc[128 + cg * 4 + j];
        ad_lo[j] = adst[cg * 4 + j];
        ad_hi[j] = adst[128 + cg * 4 + j];
    }
    int hA = cg >> 4;                           // head of low half (0/1)
    int slot = (w & 3) * 4 + cx2;               // 0..15
#pragma unroll
    for (int i = 0; i < 8; i++) {
        int r = (i < 4) ? (ry2 * 4 + i) : (32 + ry2 * 4 + (i - 4));
        float pls0 = 0, pls1 = 0, pld0 = 0, pld1 = 0;
#pragma unroll
        for (int j = 0; j < 4; j++) {
            pls0 += acc[i][j] * as_lo[j];
            pls1 += acc[i][4 + j] * as_hi[j];
            pld0 += acc[i][j] * ad_lo[j];
            pld1 += acc[i][4 + j] * ad_hi[j];
        }
        redls[r][hA][slot] = pls0;
        redls[r][2 + hA][slot] = pls1;
        redld[r][hA][slot] = pld0;
        redld[r][2 + hA][slot] = pld1;
    }
    __syncthreads();
    {
        int r = tid >> 2, h = tid & 3;
        float s = 0, d = 0;
#pragma unroll
        for (int k = 0; k < 16; k++) { s += redls[r][h][k]; d += redld[r][h][k]; }
        g_ls[(rowBase + r) * 4 + h] = s;
        g_ld[(rowBase + r) * 4 + h] = d;
    }
}

// ---------------- softmax weights v3: smem-staged, all heads per graph -------
// grid GG; 512 threads; thread-per-node; ls/ld/srcList staged in smem.
// Output: g_alpha[(g*HEADS+h)*EP + j], normalized (store-then-scale).
__global__ void __launch_bounds__(512) k_weights3() {
    __shared__ float sls[HEADS * 1000];
    __shared__ float sld[HEADS * 1000];
    __shared__ int   ssrc[EP];
    int g = blockIdx.x;
    size_t gb = (size_t)g * NN;
    int tid = threadIdx.x;
    const float* __restrict__ lsrc = g_ls + gb * HEADS;
    const float* __restrict__ ldsr = g_ld + gb * HEADS;
    for (int i = tid; i < NN * HEADS; i += 512) {
        sls[i] = lsrc[i];                 // sls[n*4+h]
        sld[i] = ldsr[i];
    }
    for (int i = tid; i < EP; i += 512)
        ssrc[i] = g_srcList[i];
    __syncthreads();

    float* __restrict__ aw0 = g_alpha + (size_t)(g * HEADS + 0) * EP;
    float* __restrict__ aw1 = g_alpha + (size_t)(g * HEADS + 1) * EP;
    float* __restrict__ aw2 = g_alpha + (size_t)(g * HEADS + 2) * EP;
    float* __restrict__ aw3 = g_alpha + (size_t)(g * HEADS + 3) * EP;

    for (int n = tid; n < NN; n += 512) {
        int s0 = g_off[n], s1 = g_off[n + 1];
        float ld0 = sld[n * 4 + 0], ld1 = sld[n * 4 + 1];
        float ld2 = sld[n * 4 + 2], ld3 = sld[n * 4 + 3];
        float sm0 = 0.f, sm1 = 0.f, sm2 = 0.f, sm3 = 0.f;
        for (int j = s0; j < s1; j++) {
            int s4 = ssrc[j] * 4;
            float v0 = sls[s4 + 0] + ld0; v0 = v0 > 0.f ? v0 : 0.2f * v0;
            float v1 = sls[s4 + 1] + ld1; v1 = v1 > 0.f ? v1 : 0.2f * v1;
            float v2 = sls[s4 + 2] + ld2; v2 = v2 > 0.f ? v2 : 0.2f * v2;
            float v3 = sls[s4 + 3] + ld3; v3 = v3 > 0.f ? v3 : 0.2f * v3;
            float w0 = __expf(v0), w1 = __expf(v1), w2 = __expf(v2), w3 = __expf(v3);
            aw0[j] = w0; aw1[j] = w1; aw2[j] = w2; aw3[j] = w3;
            sm0 += w0; sm1 += w1; sm2 += w2; sm3 += w3;
        }
        float i0 = 1.f / (sm0 + 1e-16f), i1 = 1.f / (sm1 + 1e-16f);
        float i2 = 1.f / (sm2 + 1e-16f), i3 = 1.f / (sm3 + 1e-16f);
        for (int j = s0; j < s1; j++) {
            aw0[j] *= i0; aw1[j] *= i1; aw2[j] *= i2; aw3[j] *= i3;
        }
    }
}

// ---------------- GAT aggregate (R6 champion): slice-major, half-warp/node ---
// grid (GG, 16): slice sl, head h = sl>>2. 512 threads; half-warp per node.
__global__ void __launch_bounds__(512) k_gat_agg4() {
    extern __shared__ float Hs[];               // [1000][16]
    int g = blockIdx.x, sl = blockIdx.y;
    int h = sl >> 2;
    int tid = threadIdx.x;
    int lane = tid & 31, w = tid >> 5;
    int half = lane >> 4, ch = lane & 15;
    size_t gb = (size_t)g * NN;
    float* __restrict__ Hsl = g_H + (size_t)sl * HSLICE + gb * 16;

    // Phase A: fully coalesced contiguous 64KB copy
    const float4* src4 = (const float4*)Hsl;
    for (int idx = tid; idx < NN * 4; idx += 512)
        ((float4*)Hs)[idx] = src4[idx];
    __syncthreads();

    const float* __restrict__ aw = g_alpha + (size_t)(g * HEADS + h) * EP;

    // Phase B: half-warp per node SpMM (alpha pre-normalized)
    for (int n = w * 2 + half; n < NN; n += 32) {
        int s0 = g_off[n], s1 = g_off[n + 1];
        float acc = 0.f;
        int j = s0;
        for (; j + 2 <= s1; j += 2) {
            float a0 = aw[j],        a1 = aw[j + 1];
            int   i0 = g_srcList[j], i1 = g_srcList[j + 1];
            acc += a0 * Hs[i0 * 16 + ch] + a1 * Hs[i1 * 16 + ch];
        }
        if (j < s1)
            acc += aw[j] * Hs[g_srcList[j] * 16 + ch];
        Hsl[n * 16 + ch] = acc;                 // in-place, coalesced
    }
}

// ---------------- head mean + bias + elu -> X1 (final layer only) ------------
__global__ void k_finish(const float* __restrict__ bg_l) {
    int tid = threadIdx.x;
    int r = blockIdx.x * 4 + (tid >> 6);
    int c = tid & 63;
    float v = 0.f;
#pragma unroll
    for (int h = 0; h < HEADS; h++) {
        int cc = h * 64 + c;
        v += g_H[(size_t)(cc >> 4) * HSLICE + (size_t)r * 16 + (cc & 15)];
    }
    v = 0.25f * v + bg_l[c];
    v = v > 0.f ? v : expm1f(v);
    g_X1[(size_t)r * 64 + c] = v;
}

// ---------------- GI split-K GEMM -------------------------------------------
__global__ void __launch_bounds__(256) k_gi_gemm(const float* __restrict__ Wih) {
    __shared__ float As[64][33];
    __shared__ float Ws[64][33];
    int kBase = blockIdx.x * KCH;
    int gateBase = blockIdx.y * 64;
    int tid = threadIdx.x;
    int tx = tid & 15, ty = tid >> 4;
    float acc[4][4] = {};
    for (int kt = 0; kt < KCH / 32; kt++) {
        int k0 = kBase + kt * 32;
#pragma unroll
        for (int i = 0; i < 8; i++) {
            int idx = tid + i * 256;
            int r = idx >> 5, kk = idx & 31;
            As[r][kk] = g_X1[r * NH + k0 + kk];
            Ws[r][kk] = Wih[(size_t)(gateBase + r) * NH + k0 + kk];
        }
        __syncthreads();
#pragma unroll
        for (int kk = 0; kk < 32; kk++) {
            float a[4], wv[4];
#pragma unroll
            for (int i = 0; i < 4; i++) a[i] = As[ty * 4 + i][kk];
#pragma unroll
            for (int j = 0; j < 4; j++) wv[j] = Ws[tx * 4 + j][kk];
#pragma unroll
            for (int i = 0; i < 4; i++)
#pragma unroll
                for (int j = 0; j < 4; j++)
                    acc[i][j] += a[i] * wv[j];
        }
        __syncthreads();
    }
#pragma unroll
    for (int i = 0; i < 4; i++)
#pragma unroll
        for (int j = 0; j < 4; j++)
            g_GIpart[(blockIdx.x * GG + ty * 4 + i) * GATES + gateBase + tx * 4 + j] = acc[i][j];
}

__global__ void k_gi_reduce(const float* __restrict__ b_ih) {
    int idx = blockIdx.x * blockDim.x + threadIdx.x;
    int j = idx % GATES;
    float s = b_ih[j];
    for (int kc = 0; kc < NCHUNK; kc++)
        s += g_GIpart[kc * GG * GATES + idx];
    g_GI[idx] = s;
}

// ---------------- GRU recurrence ----------------
__global__ void __launch_bounds__(256) k_gru(const float* __restrict__ Whh,
                                             const float* __restrict__ bhh) {
    __shared__ float h[BB][HID];
    __shared__ float gh[BB][GATES];
    int tid = threadIdx.x;
    h[tid >> 6][tid & 63] = 0.f;
    __syncthreads();
    for (int t = 0; t < TT; t++) {
#pragma unroll
        for (int q = 0; q < 3; q++) {
            int idx = tid + q * 256;
            int b = idx / GATES, j = idx % GATES;
            float s = bhh[j];
#pragma unroll
            for (int c = 0; c < HID; c++)
                s += h[b][c] * Whh[j * HID + c];
            gh[b][j] = s;
        }
        __syncthreads();
        int b = tid >> 6, c = tid & 63;
        int g = b * TT + t;
        float ir = g_GI[g * GATES + c]        + gh[b][c];
        float iz = g_GI[g * GATES + 64 + c]   + gh[b][64 + c];
        float in = g_GI[g * GATES + 128 + c];
        float hn = gh[b][128 + c];
        float r = 1.f / (1.f + expf(-ir));
        float z = 1.f / (1.f + expf(-iz));
        float nn = tanhf(in + r * hn);
        float hnew = (1.f - z) * nn + z * h[b][c];
        __syncthreads();
        h[b][c] = hnew;
        __syncthreads();
    }
    g_hT[tid] = h[tid >> 6][tid & 63];
}

// ---------------- final FC ----------------
__global__ void k_fc(const float* __restrict__ Wfc, const float* __restrict__ bfc,
                     float* __restrict__ out) {
    int b = blockIdx.x;
    int n = blockIdx.y * 256 + threadIdx.x;
    if (n >= NN) return;
    float s = bfc[n];
#pragma unroll
    for (int c = 0; c < HID; c++)
        s += g_hT[b * HID + c] * Wfc[c * NN + n];
    out[b * NN + n] = s;
}

// ---------------- launcher ----------------
extern "C" void kernel_launch(void* const* d_in, const int* in_sizes, int n_in,
                              void* d_out, int out_size) {
    const float* x_seq = (const float*)d_in[0];
    const int*   edge_index = (const int*)d_in[1];
    const float* W_in = (const float*)d_in[3];
    const float* b_in = (const float*)d_in[4];
    const float* Wg   = (const float*)d_in[5];
    const float* a_src= (const float*)d_in[6];
    const float* a_dst= (const float*)d_in[7];
    const float* bg   = (const float*)d_in[8];
    const float* W_ih = (const float*)d_in[9];
    const float* W_hh = (const float*)d_in[10];
    const float* b_ih = (const float*)d_in[11];
    const float* b_hh = (const float*)d_in[12];
    const float* W_fc = (const float*)d_in[13];
    const float* b_fc = (const float*)d_in[14];
    float* out = (float*)d_out;

    cudaFuncSetAttribute(k_gat_agg4,
                         cudaFuncAttributeMaxDynamicSharedMemorySize, AGG4_SMEM);

    // launches 1-3; #4 = first k_weights3 (ncu slot)
    k_csr_all<<<1, 1024>>>(edge_index);
    k_input_fc<<<RR / 4, 256>>>(x_seq, W_in, b_in);

    for (int l = 0; l < LL; l++) {
        const float* bgPrev = (l == 0) ? nullptr : (bg + (size_t)(l - 1) * HID);
        k_gat_gemm<<<RR / 64, 256>>>(bgPrev, Wg + (size_t)l * HID * 256,
                                     a_src + (size_t)l * HEADS * HID,
                                     a_dst + (size_t)l * HEADS * HID);
        k_weights3<<<GG, 512>>>();
        k_gat_agg4<<<dim3(GG, 16), 512, AGG4_SMEM>>>();
    }
    // layer-4 aggregated H -> X1 for the GRU input GEMM
    k_finish<<<RR / 4, 256>>>(bg + (size_t)(LL - 1) * HID);

    k_gi_gemm<<<dim3(NCHUNK, 3), 256>>>(W_ih);
    k_gi_reduce<<<(GG * GATES) / 256, 256>>>(b_ih);
    k_gru<<<1, 256>>>(W_hh, b_hh);
    k_fc<<<dim3(BB, 4), 256>>>(W_fc, b_fc, out);
}

// round 10
// speedup vs baseline: 1.1901x; 1.1476x over previous
#include <cuda_runtime.h>
#include <cuda_bf16.h>

// ---------------- problem constants ----------------
#define BB   4
#define TT   16
#define NN   1000
#define FIN  8
#define EE   8000
#define EP   9000          // edges + self loops
#define HID  64
#define HEADS 4
#define LL   5
#define GG   64            // B*T graphs
#define RR   64000         // G*N rows
#define NH   64000         // N*HID
#define GATES 192
#define KCH  512
#define NCHUNK 125

#define AGG4_SMEM (NN * 16 * 4)   // 64000 B

// H layout: slice-major. Column c of row r lives at
//   g_H[(c>>4) * (RR*16) + r*16 + (c&15)]
#define HSLICE (RR * 16)

// ---------------- device scratch ----------------
__device__ float g_X0[RR * HID];
__device__ float g_X1[RR * HID];
__device__ float g_H [16 * HSLICE];
__device__ float g_ls[RR * HEADS];
__device__ float g_ld[RR * HEADS];
__device__ int   g_off[NN + 1];
__device__ int   g_srcList[EP];
__device__ int   g_eid[EP];
__device__ float g_alpha[GG * HEADS * EP];   // NORMALIZED softmax weights
__device__ float g_GIpart[NCHUNK * GG * GATES];
__device__ float g_GI[GG * GATES];
__device__ float g_hT[BB * HID];

// ---------------- CSR build: ONE kernel, one block (deterministic) -----------
__global__ void __launch_bounds__(1024) k_csr_all(const int* __restrict__ edge_index) {
    __shared__ int scnt[1024];
    __shared__ int sscan[1024];
    __shared__ int scur[1024];
    int tid = threadIdx.x;
    scnt[tid] = 0;
    __syncthreads();
    for (int e = tid; e < EE; e += 1024)
        atomicAdd(&scnt[edge_index[EE + e]], 1);
    __syncthreads();
    int v = (tid < NN) ? (scnt[tid] + 1) : 0;    // +1 self loop
    sscan[tid] = v;
    __syncthreads();
    for (int o = 1; o < 1024; o <<= 1) {
        int add = (tid >= o) ? sscan[tid - o] : 0;
        __syncthreads();
        sscan[tid] += add;
        __syncthreads();
    }
    if (tid < NN) {
        g_off[tid + 1] = sscan[tid];
        scur[tid] = (tid == 0) ? 0 : sscan[tid - 1];
    }
    if (tid == 0) g_off[0] = 0;
    __syncthreads();
    for (int e = tid; e < EP; e += 1024) {
        int s, d;
        if (e < EE) { s = edge_index[e]; d = edge_index[EE + e]; }
        else        { s = e - EE;        d = e - EE; }
        int pos = atomicAdd(&scur[d], 1);
        g_srcList[pos] = s;
        g_eid[pos] = e;
    }
    __syncthreads();
    if (tid < NN) {                       // stable order by edge id
        int s0 = g_off[tid], s1 = g_off[tid + 1];
        for (int i = s0 + 1; i < s1; i++) {
            int id = g_eid[i], sv = g_srcList[i];
            int j = i - 1;
            while (j >= s0 && g_eid[j] > id) {
                g_eid[j + 1] = g_eid[j];
                g_srcList[j + 1] = g_srcList[j];
                j--;
            }
            g_eid[j + 1] = id;
            g_srcList[j + 1] = sv;
        }
    }
}

// ---------------- input projection ----------------
__global__ void k_input_fc(const float* __restrict__ x,
                           const float* __restrict__ W_in,
                           const float* __restrict__ b_in) {
    int tid = threadIdx.x;
    int r = blockIdx.x * 4 + (tid >> 6);
    int c = tid & 63;
    float s = b_in[c];
#pragma unroll
    for (int f = 0; f < FIN; f++)
        s += x[r * FIN + f] * W_in[f * HID + c];
    g_X0[r * HID + c] = s;
}

// ---------------- GAT GEMM + fused finish + fused ls/ld epilogue -------------
// bgPrev == nullptr: As from g_X0 (layer 0).
// else: As[k][r] = elu(0.25 * sum_h H_agg[r][h*64+k] + bgPrev[k])  (fused finish)
__global__ void __launch_bounds__(256) k_gat_gemm(const float* __restrict__ bgPrev,
                                                  const float* __restrict__ W,
                                                  const float* __restrict__ asrc,
                                                  const float* __restrict__ adst) {
    __shared__ float sm[12288];                 // 48KB, aliased
    float (*As)[64]  = (float(*)[64])sm;        // [64][64]
    float (*Ws)[256] = (float(*)[256])(sm + 4096); // [32][256]
    int rowBase = blockIdx.x * 64;
    int tid = threadIdx.x;

    if (bgPrev == nullptr) {
        const float4* X4 = (const float4*)(g_X0 + (size_t)rowBase * 64);
#pragma unroll
        for (int q = 0; q < 4; q++) {
            int idx = tid + q * 256;
            int r = idx & 63, k4 = idx >> 6;
            float4 v = X4[r * 16 + k4];
            As[k4 * 4 + 0][r] = v.x;
            As[k4 * 4 + 1][r] = v.y;
            As[k4 * 4 + 2][r] = v.z;
            As[k4 * 4 + 3][r] = v.w;
        }
    } else {
#pragma unroll
        for (int q = 0; q < 4; q++) {
            int idx = tid + q * 256;
            int r = idx & 63, c = (idx >> 6) * 4;    // c in {0,4,...,60}
            size_t rg = (size_t)(rowBase + r) * 16 + (c & 15);
            float4 v = make_float4(0.f, 0.f, 0.f, 0.f);
#pragma unroll
            for (int h = 0; h < HEADS; h++) {
                float4 t = *(const float4*)&g_H[(size_t)(h * 4 + (c >> 4)) * HSLICE + rg];
                v.x += t.x; v.y += t.y; v.z += t.z; v.w += t.w;
            }
            float e0 = 0.25f * v.x + bgPrev[c];
            float e1 = 0.25f * v.y + bgPrev[c + 1];
            float e2 = 0.25f * v.z + bgPrev[c + 2];
            float e3 = 0.25f * v.w + bgPrev[c + 3];
            As[c + 0][r] = e0 > 0.f ? e0 : expm1f(e0);
            As[c + 1][r] = e1 > 0.f ? e1 : expm1f(e1);
            As[c + 2][r] = e2 > 0.f ? e2 : expm1f(e2);
            As[c + 3][r] = e3 > 0.f ? e3 : expm1f(e3);
        }
    }

    int lane = tid & 31, w = tid >> 5;
    int ry2 = lane >> 2, cx2 = lane & 3;
    int cg = w * 4 + cx2;                       // 0..31
    float acc[8][8] = {};
    const float4* W4 = (const float4*)W;

#pragma unroll
    for (int half = 0; half < 2; half++) {
        __syncthreads();
#pragma unroll
        for (int q = 0; q < 8; q++) {
            int idx = tid + q * 256;
            ((float4*)Ws)[idx] = W4[half * 2048 + idx];
        }
        __syncthreads();
#pragma unroll
        for (int kk = 0; kk < 32; kk++) {
            int k = half * 32 + kk;
            float4 a0 = *(const float4*)&As[k][ry2 * 4];
            float4 a1 = *(const float4*)&As[k][32 + ry2 * 4];
            float4 b0 = *(const float4*)&Ws[kk][cg * 4];
            float4 b1 = *(const float4*)&Ws[kk][128 + cg * 4];
            float av[8] = {a0.x, a0.y, a0.z, a0.w, a1.x, a1.y, a1.z, a1.w};
            float bv[8] = {b0.x, b0.y, b0.z, b0.w, b1.x, b1.y, b1.z, b1.w};
#pragma unroll
            for (int i = 0; i < 8; i++)
#pragma unroll
                for (int j = 0; j < 8; j++)
                    acc[i][j] += av[i] * bv[j];
        }
    }
    // store H in slice-major layout
    {
        int slLo = cg >> 2, slHi = 8 + (cg >> 2);
        int chB = (cg & 3) * 4;
#pragma unroll
        for (int i = 0; i < 8; i++) {
            int r = rowBase + ((i < 4) ? (ry2 * 4 + i) : (32 + ry2 * 4 + (i - 4)));
            *(float4*)&g_H[(size_t)slLo * HSLICE + r * 16 + chB] =
                make_float4(acc[i][0], acc[i][1], acc[i][2], acc[i][3]);
            *(float4*)&g_H[(size_t)slHi * HSLICE + r * 16 + chB] =
                make_float4(acc[i][4], acc[i][5], acc[i][6], acc[i][7]);
        }
    }

    // ---- fused ls/ld epilogue ----
    __syncthreads();                            // done reading As/Ws
    float (*redls)[4][16] = (float(*)[4][16])sm;          // [64][4][16]
    float (*redld)[4][16] = (float(*)[4][16])(sm + 4096);
    float as_lo[4], as_hi[4], ad_lo[4], ad_hi[4];
#pragma unroll
    for (int j = 0; j < 4; j++) {
        as_lo[j] = asrc[cg * 4 + j];
        as_hi[j] = asrc[128 + cg * 4 + j];
        ad_lo[j] = adst[cg * 4 + j];
        ad_hi[j] = adst[128 + cg * 4 + j];
    }
    int hA = cg >> 4;                           // head of low half (0/1)
    int slot = (w & 3) * 4 + cx2;               // 0..15
#pragma unroll
    for (int i = 0; i < 8; i++) {
        int r = (i < 4) ? (ry2 * 4 + i) : (32 + ry2 * 4 + (i - 4));
        float pls0 = 0, pls1 = 0, pld0 = 0, pld1 = 0;
#pragma unroll
        for (int j = 0; j < 4; j++) {
            pls0 += acc[i][j] * as_lo[j];
            pls1 += acc[i][4 + j] * as_hi[j];
            pld0 += acc[i][j] * ad_lo[j];
            pld1 += acc[i][4 + j] * ad_hi[j];
        }
        redls[r][hA][slot] = pls0;
        redls[r][2 + hA][slot] = pls1;
        redld[r][hA][slot] = pld0;
        redld[r][2 + hA][slot] = pld1;
    }
    __syncthreads();
    {
        int r = tid >> 2, h = tid & 3;
        float s = 0, d = 0;
#pragma unroll
        for (int k = 0; k < 16; k++) { s += redls[r][h][k]; d += redld[r][h][k]; }
        g_ls[(rowBase + r) * 4 + h] = s;
        g_ld[(rowBase + r) * 4 + h] = d;
    }
}

// ---------------- softmax weights v4: grid (GG,HEADS) + smem-staged ls/ld ----
// 256 blocks, 512 threads; thread-per-node; ls/ld for THIS head staged in smem
// via coalesced float4 loads of the 4-head records. Store-then-scale normalize.
__global__ void __launch_bounds__(512) k_weights4() {
    __shared__ float sls[1000];
    __shared__ float sld[1000];
    int g = blockIdx.x, h = blockIdx.y;
    size_t gb = (size_t)g * NN;
    int tid = threadIdx.x;
    const float4* __restrict__ ls4 = (const float4*)(g_ls + gb * HEADS);
    const float4* __restrict__ ld4 = (const float4*)(g_ld + gb * HEADS);
    for (int n = tid; n < NN; n += 512) {
        float4 a = ls4[n];
        float4 b = ld4[n];
        sls[n] = ((const float*)&a)[h];
        sld[n] = ((const float*)&b)[h];
    }
    __syncthreads();

    float* __restrict__ aw = g_alpha + (size_t)(g * HEADS + h) * EP;
    for (int n = tid; n < NN; n += 512) {
        int s0 = g_off[n], s1 = g_off[n + 1];
        float ldv = sld[n];
        float sum = 0.f;
        for (int j = s0; j < s1; j++) {
            int s = g_srcList[j];
            float v = sls[s] + ldv;
            v = v > 0.f ? v : 0.2f * v;
            float wv = __expf(v);
            aw[j] = wv;
            sum += wv;
        }
        float inv = 1.f / (sum + 1e-16f);
        for (int j = s0; j < s1; j++)
            aw[j] *= inv;
    }
}

// ---------------- GAT aggregate (champion): slice-major, half-warp/node ------
// grid (GG, 16): slice sl, head h = sl>>2. 512 threads; half-warp per node.
__global__ void __launch_bounds__(512) k_gat_agg4() {
    extern __shared__ float Hs[];               // [1000][16]
    int g = blockIdx.x, sl = blockIdx.y;
    int h = sl >> 2;
    int tid = threadIdx.x;
    int lane = tid & 31, w = tid >> 5;
    int half = lane >> 4, ch = lane & 15;
    size_t gb = (size_t)g * NN;
    float* __restrict__ Hsl = g_H + (size_t)sl * HSLICE + gb * 16;

    // Phase A: fully coalesced contiguous 64KB copy
    const float4* src4 = (const float4*)Hsl;
    for (int idx = tid; idx < NN * 4; idx += 512)
        ((float4*)Hs)[idx] = src4[idx];
    __syncthreads();

    const float* __restrict__ aw = g_alpha + (size_t)(g * HEADS + h) * EP;

    // Phase B: half-warp per node SpMM (alpha pre-normalized)
    for (int n = w * 2 + half; n < NN; n += 32) {
        int s0 = g_off[n], s1 = g_off[n + 1];
        float acc = 0.f;
        int j = s0;
        for (; j + 2 <= s1; j += 2) {
            float a0 = aw[j],        a1 = aw[j + 1];
            int   i0 = g_srcList[j], i1 = g_srcList[j + 1];
            acc += a0 * Hs[i0 * 16 + ch] + a1 * Hs[i1 * 16 + ch];
        }
        if (j < s1)
            acc += aw[j] * Hs[g_srcList[j] * 16 + ch];
        Hsl[n * 16 + ch] = acc;                 // in-place, coalesced
    }
}

// ---------------- head mean + bias + elu -> X1 (final layer only) ------------
__global__ void k_finish(const float* __restrict__ bg_l) {
    int tid = threadIdx.x;
    int r = blockIdx.x * 4 + (tid >> 6);
    int c = tid & 63;
    float v = 0.f;
#pragma unroll
    for (int h = 0; h < HEADS; h++) {
        int cc = h * 64 + c;
        v += g_H[(size_t)(cc >> 4) * HSLICE + (size_t)r * 16 + (cc & 15)];
    }
    v = 0.25f * v + bg_l[c];
    v = v > 0.f ? v : expm1f(v);
    g_X1[(size_t)r * 64 + c] = v;
}

// ---------------- GI split-K GEMM -------------------------------------------
__global__ void __launch_bounds__(256) k_gi_gemm(const float* __restrict__ Wih) {
    __shared__ float As[64][33];
    __shared__ float Ws[64][33];
    int kBase = blockIdx.x * KCH;
    int gateBase = blockIdx.y * 64;
    int tid = threadIdx.x;
    int tx = tid & 15, ty = tid >> 4;
    float acc[4][4] = {};
    for (int kt = 0; kt < KCH / 32; kt++) {
        int k0 = kBase + kt * 32;
#pragma unroll
        for (int i = 0; i < 8; i++) {
            int idx = tid + i * 256;
            int r = idx >> 5, kk = idx & 31;
            As[r][kk] = g_X1[r * NH + k0 + kk];
            Ws[r][kk] = Wih[(size_t)(gateBase + r) * NH + k0 + kk];
        }
        __syncthreads();
#pragma unroll
        for (int kk = 0; kk < 32; kk++) {
            float a[4], wv[4];
#pragma unroll
            for (int i = 0; i < 4; i++) a[i] = As[ty * 4 + i][kk];
#pragma unroll
            for (int j = 0; j < 4; j++) wv[j] = Ws[tx * 4 + j][kk];
#pragma unroll
            for (int i = 0; i < 4; i++)
#pragma unroll
                for (int j = 0; j < 4; j++)
                    acc[i][j] += a[i] * wv[j];
        }
        __syncthreads();
    }
#pragma unroll
    for (int i = 0; i < 4; i++)
#pragma unroll
        for (int j = 0; j < 4; j++)
            g_GIpart[(blockIdx.x * GG + ty * 4 + i) * GATES + gateBase + tx * 4 + j] = acc[i][j];
}

__global__ void k_gi_reduce(const float* __restrict__ b_ih) {
    int idx = blockIdx.x * blockDim.x + threadIdx.x;
    int j = idx % GATES;
    float s = b_ih[j];
    for (int kc = 0; kc < NCHUNK; kc++)
        s += g_GIpart[kc * GG * GATES + idx];
    g_GI[idx] = s;
}

// ---------------- GRU recurrence ----------------
__global__ void __launch_bounds__(256) k_gru(const float* __restrict__ Whh,
                                             const float* __restrict__ bhh) {
    __shared__ float h[BB][HID];
    __shared__ float gh[BB][GATES];
    int tid = threadIdx.x;
    h[tid >> 6][tid & 63] = 0.f;
    __syncthreads();
    for (int t = 0; t < TT; t++) {
#pragma unroll
        for (int q = 0; q < 3; q++) {
            int idx = tid + q * 256;
            int b = idx / GATES, j = idx % GATES;
            float s = bhh[j];
#pragma unroll
            for (int c = 0; c < HID; c++)
                s += h[b][c] * Whh[j * HID + c];
            gh[b][j] = s;
        }
        __syncthreads();
        int b = tid >> 6, c = tid & 63;
        int g = b * TT + t;
        float ir = g_GI[g * GATES + c]        + gh[b][c];
        float iz = g_GI[g * GATES + 64 + c]   + gh[b][64 + c];
        float in = g_GI[g * GATES + 128 + c];
        float hn = gh[b][128 + c];
        float r = 1.f / (1.f + expf(-ir));
        float z = 1.f / (1.f + expf(-iz));
        float nn = tanhf(in + r * hn);
        float hnew = (1.f - z) * nn + z * h[b][c];
        __syncthreads();
        h[b][c] = hnew;
        __syncthreads();
    }
    g_hT[tid] = h[tid >> 6][tid & 63];
}

// ---------------- final FC ----------------
__global__ void k_fc(const float* __restrict__ Wfc, const float* __restrict__ bfc,
                     float* __restrict__ out) {
    int b = blockIdx.x;
    int n = blockIdx.y * 256 + threadIdx.x;
    if (n >= NN) return;
    float s = bfc[n];
#pragma unroll
    for (int c = 0; c < HID; c++)
        s += g_hT[b * HID + c] * Wfc[c * NN + n];
    out[b * NN + n] = s;
}

// ---------------- launcher ----------------
extern "C" void kernel_launch(void* const* d_in, const int* in_sizes, int n_in,
                              void* d_out, int out_size) {
    const float* x_seq = (const float*)d_in[0];
    const int*   edge_index = (const int*)d_in[1];
    const float* W_in = (const float*)d_in[3];
    const float* b_in = (const float*)d_in[4];
    const float* Wg   = (const float*)d_in[5];
    const float* a_src= (const float*)d_in[6];
    const float* a_dst= (const float*)d_in[7];
    const float* bg   = (const float*)d_in[8];
    const float* W_ih = (const float*)d_in[9];
    const float* W_hh = (const float*)d_in[10];
    const float* b_ih = (const float*)d_in[11];
    const float* b_hh = (const float*)d_in[12];
    const float* W_fc = (const float*)d_in[13];
    const float* b_fc = (const float*)d_in[14];
    float* out = (float*)d_out;

    cudaFuncSetAttribute(k_gat_agg4,
                         cudaFuncAttributeMaxDynamicSharedMemorySize, AGG4_SMEM);

    // launches 1-3; #4 = first k_weights4 (ncu slot)
    k_csr_all<<<1, 1024>>>(edge_index);
    k_input_fc<<<RR / 4, 256>>>(x_seq, W_in, b_in);

    for (int l = 0; l < LL; l++) {
        const float* bgPrev = (l == 0) ? nullptr : (bg + (size_t)(l - 1) * HID);
        k_gat_gemm<<<RR / 64, 256>>>(bgPrev, Wg + (size_t)l * HID * 256,
                                     a_src + (size_t)l * HEADS * HID,
                                     a_dst + (size_t)l * HEADS * HID);
        k_weights4<<<dim3(GG, HEADS), 512>>>();
        k_gat_agg4<<<dim3(GG, 16), 512, AGG4_SMEM>>>();
    }
    // layer-4 aggregated H -> X1 for the GRU input GEMM
    k_finish<<<RR / 4, 256>>>(bg + (size_t)(LL - 1) * HID);

    k_gi_gemm<<<dim3(NCHUNK, 3), 256>>>(W_ih);
    k_gi_reduce<<<(GG * GATES) / 256, 256>>>(b_ih);
    k_gru<<<1, 256>>>(W_hh, b_hh);
    k_fc<<<dim3(BB, 4), 256>>>(W_fc, b_fc, out);
}

// round 11
// speedup vs baseline: 1.2462x; 1.0471x over previous
#include <cuda_runtime.h>
#include <cuda_bf16.h>

// ---------------- problem constants ----------------
#define BB   4
#define TT   16
#define NN   1000
#define FIN  8
#define EE   8000
#define EP   9000          // edges + self loops
#define HID  64
#define HEADS 4
#define LL   5
#define GG   64            // B*T graphs
#define RR   64000         // G*N rows
#define NH   64000         // N*HID
#define GATES 192
#define KCH  512
#define NCHUNK 125

// H layout: slice-major. Column c of row r lives at
//   g_H[(c>>4) * (RR*16) + r*16 + (c&15)]
#define HSLICE (RR * 16)

// agg5: two 16-ch halves with 16-word pad between (bank rotation)
#define AGG5_PAD   16
#define AGG5_HALF  (NN * 16)                      // 16000 floats
#define AGG5_SMEM  ((2 * AGG5_HALF + AGG5_PAD) * 4)   // 128064 B

// ---------------- device scratch ----------------
__device__ float g_X0[RR * HID];
__device__ float g_X1[RR * HID];
__device__ float g_H [16 * HSLICE];
__device__ float g_ls[RR * HEADS];
__device__ float g_ld[RR * HEADS];
__device__ int   g_off[NN + 1];
__device__ int   g_srcList[EP];
__device__ int   g_eid[EP];
__device__ float g_alpha[GG * HEADS * EP];   // NORMALIZED softmax weights
__device__ float g_GIpart[NCHUNK * GG * GATES];
__device__ float g_GI[GG * GATES];
__device__ float g_hT[BB * HID];

// ---------------- fused pre-kernel: input proj (blocks 0-3999) + CSR (4000) --
__global__ void __launch_bounds__(1024) k_pre(const int* __restrict__ edge_index,
                                              const float* __restrict__ x,
                                              const float* __restrict__ W_in,
                                              const float* __restrict__ b_in) {
    int tid = threadIdx.x;
    if (blockIdx.x < 4000) {
        int r = blockIdx.x * 16 + (tid >> 6);
        int c = tid & 63;
        float s = b_in[c];
#pragma unroll
        for (int f = 0; f < FIN; f++)
            s += x[r * FIN + f] * W_in[f * HID + c];
        g_X0[r * HID + c] = s;
        return;
    }
    // ---- CSR build (deterministic), one block ----
    __shared__ int scnt[1024];
    __shared__ int sscan[1024];
    __shared__ int scur[1024];
    scnt[tid] = 0;
    __syncthreads();
    for (int e = tid; e < EE; e += 1024)
        atomicAdd(&scnt[edge_index[EE + e]], 1);
    __syncthreads();
    int v = (tid < NN) ? (scnt[tid] + 1) : 0;    // +1 self loop
    sscan[tid] = v;
    __syncthreads();
    for (int o = 1; o < 1024; o <<= 1) {
        int add = (tid >= o) ? sscan[tid - o] : 0;
        __syncthreads();
        sscan[tid] += add;
        __syncthreads();
    }
    if (tid < NN) {
        g_off[tid + 1] = sscan[tid];
        scur[tid] = (tid == 0) ? 0 : sscan[tid - 1];
    }
    if (tid == 0) g_off[0] = 0;
    __syncthreads();
    for (int e = tid; e < EP; e += 1024) {
        int s, d;
        if (e < EE) { s = edge_index[e]; d = edge_index[EE + e]; }
        else        { s = e - EE;        d = e - EE; }
        int pos = atomicAdd(&scur[d], 1);
        g_srcList[pos] = s;
        g_eid[pos] = e;
    }
    __syncthreads();
    if (tid < NN) {                       // stable order by edge id
        int s0 = g_off[tid], s1 = g_off[tid + 1];
        for (int i = s0 + 1; i < s1; i++) {
            int id = g_eid[i], sv = g_srcList[i];
            int j = i - 1;
            while (j >= s0 && g_eid[j] > id) {
                g_eid[j + 1] = g_eid[j];
                g_srcList[j + 1] = g_srcList[j];
                j--;
            }
            g_eid[j + 1] = id;
            g_srcList[j + 1] = sv;
        }
    }
}

// ---------------- GAT GEMM + fused finish + fused ls/ld epilogue -------------
// bgPrev == nullptr: As from g_X0 (layer 0).
// else: As[k][r] = elu(0.25 * sum_h H_agg[r][h*64+k] + bgPrev[k])
__global__ void __launch_bounds__(256) k_gat_gemm(const float* __restrict__ bgPrev,
                                                  const float* __restrict__ W,
                                                  const float* __restrict__ asrc,
                                                  const float* __restrict__ adst) {
    __shared__ float sm[12288];                 // 48KB, aliased
    float (*As)[64]  = (float(*)[64])sm;        // [64][64]
    float (*Ws)[256] = (float(*)[256])(sm + 4096); // [32][256]
    int rowBase = blockIdx.x * 64;
    int tid = threadIdx.x;

    if (bgPrev == nullptr) {
        const float4* X4 = (const float4*)(g_X0 + (size_t)rowBase * 64);
#pragma unroll
        for (int q = 0; q < 4; q++) {
            int idx = tid + q * 256;
            int r = idx & 63, k4 = idx >> 6;
            float4 v = X4[r * 16 + k4];
            As[k4 * 4 + 0][r] = v.x;
            As[k4 * 4 + 1][r] = v.y;
            As[k4 * 4 + 2][r] = v.z;
            As[k4 * 4 + 3][r] = v.w;
        }
    } else {
#pragma unroll
        for (int q = 0; q < 4; q++) {
            int idx = tid + q * 256;
            int r = idx & 63, c = (idx >> 6) * 4;    // c in {0,4,...,60}
            size_t rg = (size_t)(rowBase + r) * 16 + (c & 15);
            float4 v = make_float4(0.f, 0.f, 0.f, 0.f);
#pragma unroll
            for (int h = 0; h < HEADS; h++) {
                float4 t = *(const float4*)&g_H[(size_t)(h * 4 + (c >> 4)) * HSLICE + rg];
                v.x += t.x; v.y += t.y; v.z += t.z; v.w += t.w;
            }
            float e0 = 0.25f * v.x + bgPrev[c];
            float e1 = 0.25f * v.y + bgPrev[c + 1];
            float e2 = 0.25f * v.z + bgPrev[c + 2];
            float e3 = 0.25f * v.w + bgPrev[c + 3];
            As[c + 0][r] = e0 > 0.f ? e0 : expm1f(e0);
            As[c + 1][r] = e1 > 0.f ? e1 : expm1f(e1);
            As[c + 2][r] = e2 > 0.f ? e2 : expm1f(e2);
            As[c + 3][r] = e3 > 0.f ? e3 : expm1f(e3);
        }
    }

    int lane = tid & 31, w = tid >> 5;
    int ry2 = lane >> 2, cx2 = lane & 3;
    int cg = w * 4 + cx2;                       // 0..31
    float acc[8][8] = {};
    const float4* W4 = (const float4*)W;

#pragma unroll
    for (int half = 0; half < 2; half++) {
        __syncthreads();
#pragma unroll
        for (int q = 0; q < 8; q++) {
            int idx = tid + q * 256;
            ((float4*)Ws)[idx] = W4[half * 2048 + idx];
        }
        __syncthreads();
#pragma unroll
        for (int kk = 0; kk < 32; kk++) {
            int k = half * 32 + kk;
            float4 a0 = *(const float4*)&As[k][ry2 * 4];
            float4 a1 = *(const float4*)&As[k][32 + ry2 * 4];
            float4 b0 = *(const float4*)&Ws[kk][cg * 4];
            float4 b1 = *(const float4*)&Ws[kk][128 + cg * 4];
            float av[8] = {a0.x, a0.y, a0.z, a0.w, a1.x, a1.y, a1.z, a1.w};
            float bv[8] = {b0.x, b0.y, b0.z, b0.w, b1.x, b1.y, b1.z, b1.w};
#pragma unroll
            for (int i = 0; i < 8; i++)
#pragma unroll
                for (int j = 0; j < 8; j++)
                    acc[i][j] += av[i] * bv[j];
        }
    }
    // store H in slice-major layout
    {
        int slLo = cg >> 2, slHi = 8 + (cg >> 2);
        int chB = (cg & 3) * 4;
#pragma unroll
        for (int i = 0; i < 8; i++) {
            int r = rowBase + ((i < 4) ? (ry2 * 4 + i) : (32 + ry2 * 4 + (i - 4)));
            *(float4*)&g_H[(size_t)slLo * HSLICE + r * 16 + chB] =
                make_float4(acc[i][0], acc[i][1], acc[i][2], acc[i][3]);
            *(float4*)&g_H[(size_t)slHi * HSLICE + r * 16 + chB] =
                make_float4(acc[i][4], acc[i][5], acc[i][6], acc[i][7]);
        }
    }

    // ---- fused ls/ld epilogue ----
    __syncthreads();                            // done reading As/Ws
    float (*redls)[4][16] = (float(*)[4][16])sm;          // [64][4][16]
    float (*redld)[4][16] = (float(*)[4][16])(sm + 4096);
    float as_lo[4], as_hi[4], ad_lo[4], ad_hi[4];
#pragma unroll
    for (int j = 0; j < 4; j++) {
        as_lo[j] = asrc[cg * 4 + j];
        as_hi[j] = asrc[128 + cg * 4 + j];
        ad_lo[j] = adst[cg * 4 + j];
        ad_hi[j] = adst[128 + cg * 4 + j];
    }
    int hA = cg >> 4;                           // head of low half (0/1)
    int slot = (w & 3) * 4 + cx2;               // 0..15
#pragma unroll
    for (int i = 0; i < 8; i++) {
        int r = (i < 4) ? (ry2 * 4 + i) : (32 + ry2 * 4 + (i - 4));
        float pls0 = 0, pls1 = 0, pld0 = 0, pld1 = 0;
#pragma unroll
        for (int j = 0; j < 4; j++) {
            pls0 += acc[i][j] * as_lo[j];
            pls1 += acc[i][4 + j] * as_hi[j];
            pld0 += acc[i][j] * ad_lo[j];
            pld1 += acc[i][4 + j] * ad_hi[j];
        }
        redls[r][hA][slot] = pls0;
        redls[r][2 + hA][slot] = pls1;
        redld[r][hA][slot] = pld0;
        redld[r][2 + hA][slot] = pld1;
    }
    __syncthreads();
    {
        int r = tid >> 2, h = tid & 3;
        float s = 0, d = 0;
#pragma unroll
        for (int k = 0; k < 16; k++) { s += redls[r][h][k]; d += redld[r][h][k]; }
        g_ls[(rowBase + r) * 4 + h] = s;
        g_ld[(rowBase + r) * 4 + h] = d;
    }
}

// ---------------- softmax weights v5: smem-buffered wv, single store pass ----
// grid (GG, HEADS); 512 threads; thread-per-node.
__global__ void __launch_bounds__(512) k_weights5() {
    __shared__ float sls[1000];
    __shared__ float sld[1000];
    __shared__ float swv[EP];
    int g = blockIdx.x, h = blockIdx.y;
    size_t gb = (size_t)g * NN;
    int tid = threadIdx.x;
    const float4* __restrict__ ls4 = (const float4*)(g_ls + gb * HEADS);
    const float4* __restrict__ ld4 = (const float4*)(g_ld + gb * HEADS);
    for (int n = tid; n < NN; n += 512) {
        float4 a = ls4[n];
        float4 b = ld4[n];
        sls[n] = ((const float*)&a)[h];
        sld[n] = ((const float*)&b)[h];
    }
    __syncthreads();

    float* __restrict__ aw = g_alpha + (size_t)(g * HEADS + h) * EP;
    for (int n = tid; n < NN; n += 512) {
        int s0 = g_off[n], s1 = g_off[n + 1];
        float ldv = sld[n];
        float sum = 0.f;
        for (int j = s0; j < s1; j++) {
            int s = g_srcList[j];
            float v = sls[s] + ldv;
            v = v > 0.f ? v : 0.2f * v;
            float wv = __expf(v);
            swv[j] = wv;
            sum += wv;
        }
        float inv = 1.f / (sum + 1e-16f);
        for (int j = s0; j < s1; j++)
            aw[j] = swv[j] * inv;               // single global store pass
    }
}

// ---------------- GAT aggregate v5: 32 channels/block, full warp/node --------
// grid (GG, 8): sl2 covers slices {sl2*2, sl2*2+1}; head h = sl2>>1.
// 1024 threads = 32 warps; warp-per-node; ch = lane spans both 16-ch halves.
// smem: Hs0[16000] | pad 16 | Hs1[16000] -> lanes 0-15 and 16-31 hit
// complementary bank halves (16016 % 32 == 16) => conflict-free LDS.
__global__ void __launch_bounds__(1024) k_gat_agg5() {
    extern __shared__ float Hs[];
    int g = blockIdx.x, sl2 = blockIdx.y;
    int sl0 = sl2 * 2;
    int h = sl2 >> 1;
    int tid = threadIdx.x;
    int lane = tid & 31, w = tid >> 5;
    size_t gb = (size_t)g * NN;
    float* __restrict__ H0 = g_H + (size_t)sl0 * HSLICE + gb * 16;
    float* __restrict__ H1 = g_H + (size_t)(sl0 + 1) * HSLICE + gb * 16;

    // Phase A: two contiguous 64KB copies (fully coalesced, conflict-free)
    {
        const float4* s0 = (const float4*)H0;
        const float4* s1 = (const float4*)H1;
        float4* d0 = (float4*)Hs;
        float4* d1 = (float4*)(Hs + AGG5_HALF + AGG5_PAD);
        for (int idx = tid; idx < NN * 4; idx += 1024) {
            d0[idx] = s0[idx];
            d1[idx] = s1[idx];
        }
    }
    __syncthreads();

    const float* __restrict__ aw = g_alpha + (size_t)(g * HEADS + h) * EP;
    int chOff = (lane >> 4) * (AGG5_HALF + AGG5_PAD) + (lane & 15);
    float* __restrict__ Hout = ((lane < 16) ? H0 : H1) + (lane & 15);

    // Phase B: warp per node; every instruction serves 32 channels
    for (int n = w; n < NN; n += 32) {
        int s0 = g_off[n], s1 = g_off[n + 1];
        float acc = 0.f;
        int j = s0;
        for (; j + 2 <= s1; j += 2) {
            float a0 = aw[j],        a1 = aw[j + 1];
            int   i0 = g_srcList[j], i1 = g_srcList[j + 1];
            acc += a0 * Hs[i0 * 16 + chOff] + a1 * Hs[i1 * 16 + chOff];
        }
        if (j < s1)
            acc += aw[j] * Hs[g_srcList[j] * 16 + chOff];
        Hout[n * 16] = acc;                     // in-place, 2x64B per warp
    }
}

// ---------------- head mean + bias + elu -> X1 (final layer only) ------------
__global__ void k_finish(const float* __restrict__ bg_l) {
    int tid = threadIdx.x;
    int r = blockIdx.x * 4 + (tid >> 6);
    int c = tid & 63;
    float v = 0.f;
#pragma unroll
    for (int h = 0; h < HEADS; h++) {
        int cc = h * 64 + c;
        v += g_H[(size_t)(cc >> 4) * HSLICE + (size_t)r * 16 + (cc & 15)];
    }
    v = 0.25f * v + bg_l[c];
    v = v > 0.f ? v : expm1f(v);
    g_X1[(size_t)r * 64 + c] = v;
}

// ---------------- GI split-K GEMM -------------------------------------------
__global__ void __launch_bounds__(256) k_gi_gemm(const float* __restrict__ Wih) {
    __shared__ float As[64][33];
    __shared__ float Ws[64][33];
    int kBase = blockIdx.x * KCH;
    int gateBase = blockIdx.y * 64;
    int tid = threadIdx.x;
    int tx = tid & 15, ty = tid >> 4;
    float acc[4][4] = {};
    for (int kt = 0; kt < KCH / 32; kt++) {
        int k0 = kBase + kt * 32;
#pragma unroll
        for (int i = 0; i < 8; i++) {
            int idx = tid + i * 256;
            int r = idx >> 5, kk = idx & 31;
            As[r][kk] = g_X1[r * NH + k0 + kk];
            Ws[r][kk] = Wih[(size_t)(gateBase + r) * NH + k0 + kk];
        }
        __syncthreads();
#pragma unroll
        for (int kk = 0; kk < 32; kk++) {
            float a[4], wv[4];
#pragma unroll
            for (int i = 0; i < 4; i++) a[i] = As[ty * 4 + i][kk];
#pragma unroll
            for (int j = 0; j < 4; j++) wv[j] = Ws[tx * 4 + j][kk];
#pragma unroll
            for (int i = 0; i < 4; i++)
#pragma unroll
                for (int j = 0; j < 4; j++)
                    acc[i][j] += a[i] * wv[j];
        }
        __syncthreads();
    }
#pragma unroll
    for (int i = 0; i < 4; i++)
#pragma unroll
        for (int j = 0; j < 4; j++)
            g_GIpart[(blockIdx.x * GG + ty * 4 + i) * GATES + gateBase + tx * 4 + j] = acc[i][j];
}

__global__ void k_gi_reduce(const float* __restrict__ b_ih) {
    int idx = blockIdx.x * blockDim.x + threadIdx.x;
    int j = idx % GATES;
    float s = b_ih[j];
    for (int kc = 0; kc < NCHUNK; kc++)
        s += g_GIpart[kc * GG * GATES + idx];
    g_GI[idx] = s;
}

// ---------------- GRU recurrence ----------------
__global__ void __launch_bounds__(256) k_gru(const float* __restrict__ Whh,
                                             const float* __restrict__ bhh) {
    __shared__ float h[BB][HID];
    __shared__ float gh[BB][GATES];
    int tid = threadIdx.x;
    h[tid >> 6][tid & 63] = 0.f;
    __syncthreads();
    for (int t = 0; t < TT; t++) {
#pragma unroll
        for (int q = 0; q < 3; q++) {
            int idx = tid + q * 256;
            int b = idx / GATES, j = idx % GATES;
            float s = bhh[j];
#pragma unroll
            for (int c = 0; c < HID; c++)
                s += h[b][c] * Whh[j * HID + c];
            gh[b][j] = s;
        }
        __syncthreads();
        int b = tid >> 6, c = tid & 63;
        int g = b * TT + t;
        float ir = g_GI[g * GATES + c]        + gh[b][c];
        float iz = g_GI[g * GATES + 64 + c]   + gh[b][64 + c];
        float in = g_GI[g * GATES + 128 + c];
        float hn = gh[b][128 + c];
        float r = 1.f / (1.f + expf(-ir));
        float z = 1.f / (1.f + expf(-iz));
        float nn = tanhf(in + r * hn);
        float hnew = (1.f - z) * nn + z * h[b][c];
        __syncthreads();
        h[b][c] = hnew;
        __syncthreads();
    }
    g_hT[tid] = h[tid >> 6][tid & 63];
}

// ---------------- final FC ----------------
__global__ void k_fc(const float* __restrict__ Wfc, const float* __restrict__ bfc,
                     float* __restrict__ out) {
    int b = blockIdx.x;
    int n = blockIdx.y * 256 + threadIdx.x;
    if (n >= NN) return;
    float s = bfc[n];
#pragma unroll
    for (int c = 0; c < HID; c++)
        s += g_hT[b * HID + c] * Wfc[c * NN + n];
    out[b * NN + n] = s;
}

// ---------------- launcher ----------------
extern "C" void kernel_launch(void* const* d_in, const int* in_sizes, int n_in,
                              void* d_out, int out_size) {
    const float* x_seq = (const float*)d_in[0];
    const int*   edge_index = (const int*)d_in[1];
    const float* W_in = (const float*)d_in[3];
    const float* b_in = (const float*)d_in[4];
    const float* Wg   = (const float*)d_in[5];
    const float* a_src= (const float*)d_in[6];
    const float* a_dst= (const float*)d_in[7];
    const float* bg   = (const float*)d_in[8];
    const float* W_ih = (const float*)d_in[9];
    const float* W_hh = (const float*)d_in[10];
    const float* b_ih = (const float*)d_in[11];
    const float* b_hh = (const float*)d_in[12];
    const float* W_fc = (const float*)d_in[13];
    const float* b_fc = (const float*)d_in[14];
    float* out = (float*)d_out;

    cudaFuncSetAttribute(k_gat_agg5,
                         cudaFuncAttributeMaxDynamicSharedMemorySize, AGG5_SMEM);

    // launch 1: fused input proj + CSR
    k_pre<<<4001, 1024>>>(edge_index, x_seq, W_in, b_in);

    // launches 2-4: gemm, weights5, agg5 (#4 = ncu slot -> agg5)
    for (int l = 0; l < LL; l++) {
        const float* bgPrev = (l == 0) ? nullptr : (bg + (size_t)(l - 1) * HID);
        k_gat_gemm<<<RR / 64, 256>>>(bgPrev, Wg + (size_t)l * HID * 256,
                                     a_src + (size_t)l * HEADS * HID,
                                     a_dst + (size_t)l * HEADS * HID);
        k_weights5<<<dim3(GG, HEADS), 512>>>();
        k_gat_agg5<<<dim3(GG, 8), 1024, AGG5_SMEM>>>();
    }
    // layer-4 aggregated H -> X1 for the GRU input GEMM
    k_finish<<<RR / 4, 256>>>(bg + (size_t)(LL - 1) * HID);

    k_gi_gemm<<<dim3(NCHUNK, 3), 256>>>(W_ih);
    k_gi_reduce<<<(GG * GATES) / 256, 256>>>(b_ih);
    k_gru<<<1, 256>>>(W_hh, b_hh);
    k_fc<<<dim3(BB, 4), 256>>>(W_fc, b_fc, out);
}

// round 12
// speedup vs baseline: 1.3144x; 1.0547x over previous
#include <cuda_runtime.h>
#include <cuda_bf16.h>

// ---------------- problem constants ----------------
#define BB   4
#define TT   16
#define NN   1000
#define FIN  8
#define EE   8000
#define EP   9000          // edges + self loops
#define HID  64
#define HEADS 4
#define LL   5
#define GG   64            // B*T graphs
#define RR   64000         // G*N rows
#define NH   64000         // N*HID
#define GATES 192
#define KCH  512
#define NCHUNK 125

// H layout: slice-major. Column c of row r lives at
//   g_H[(c>>4) * (RR*16) + r*16 + (c&15)]
#define HSLICE (RR * 16)

// agg6 smem layout (floats):
//   Hs0[16000] | pad 16 | Hs1[16000] | swv[9000] | ssrc[9000] | sls[1000] | sld[1000]
#define AGG6_PAD    16
#define AGG6_HALF   (NN * 16)
#define AGG6_SWV    (2 * AGG6_HALF + AGG6_PAD)            // 32016
#define AGG6_SSRC   (AGG6_SWV + EP)                       // 41016
#define AGG6_SLS    (AGG6_SSRC + EP)                      // 50016
#define AGG6_SLD    (AGG6_SLS + NN)                       // 51016
#define AGG6_SMEM   ((AGG6_SLD + NN) * 4)                 // 208064 B

// ---------------- device scratch ----------------
__device__ float g_X0[RR * HID];
__device__ float g_X1[RR * HID];
__device__ float g_H [16 * HSLICE];
__device__ float g_ls[RR * HEADS];
__device__ float g_ld[RR * HEADS];
__device__ int   g_off[NN + 1];
__device__ int   g_srcList[EP];
__device__ int   g_eid[EP];
__device__ float g_GIpart[NCHUNK * GG * GATES];
__device__ float g_GI[GG * GATES];
__device__ float g_hT[BB * HID];

// ---------------- CSR build: ONE kernel, one block (deterministic) -----------
__global__ void __launch_bounds__(1024) k_csr_all(const int* __restrict__ edge_index) {
    __shared__ int scnt[1024];
    __shared__ int sscan[1024];
    __shared__ int scur[1024];
    int tid = threadIdx.x;
    scnt[tid] = 0;
    __syncthreads();
    for (int e = tid; e < EE; e += 1024)
        atomicAdd(&scnt[edge_index[EE + e]], 1);
    __syncthreads();
    int v = (tid < NN) ? (scnt[tid] + 1) : 0;    // +1 self loop
    sscan[tid] = v;
    __syncthreads();
    for (int o = 1; o < 1024; o <<= 1) {
        int add = (tid >= o) ? sscan[tid - o] : 0;
        __syncthreads();
        sscan[tid] += add;
        __syncthreads();
    }
    if (tid < NN) {
        g_off[tid + 1] = sscan[tid];
        scur[tid] = (tid == 0) ? 0 : sscan[tid - 1];
    }
    if (tid == 0) g_off[0] = 0;
    __syncthreads();
    for (int e = tid; e < EP; e += 1024) {
        int s, d;
        if (e < EE) { s = edge_index[e]; d = edge_index[EE + e]; }
        else        { s = e - EE;        d = e - EE; }
        int pos = atomicAdd(&scur[d], 1);
        g_srcList[pos] = s;
        g_eid[pos] = e;
    }
    __syncthreads();
    if (tid < NN) {                       // stable order by edge id
        int s0 = g_off[tid], s1 = g_off[tid + 1];
        for (int i = s0 + 1; i < s1; i++) {
            int id = g_eid[i], sv = g_srcList[i];
            int j = i - 1;
            while (j >= s0 && g_eid[j] > id) {
                g_eid[j + 1] = g_eid[j];
                g_srcList[j + 1] = g_srcList[j];
                j--;
            }
            g_eid[j + 1] = id;
            g_srcList[j + 1] = sv;
        }
    }
}

// ---------------- input projection ----------------
__global__ void k_input_fc(const float* __restrict__ x,
                           const float* __restrict__ W_in,
                           const float* __restrict__ b_in) {
    int tid = threadIdx.x;
    int r = blockIdx.x * 4 + (tid >> 6);
    int c = tid & 63;
    float s = b_in[c];
#pragma unroll
    for (int f = 0; f < FIN; f++)
        s += x[r * FIN + f] * W_in[f * HID + c];
    g_X0[r * HID + c] = s;
}

// ---------------- GAT GEMM + fused finish + fused ls/ld epilogue -------------
// bgPrev == nullptr: As from g_X0 (layer 0).
// else: As[k][r] = elu(0.25 * sum_h H_agg[r][h*64+k] + bgPrev[k])
__global__ void __launch_bounds__(256) k_gat_gemm(const float* __restrict__ bgPrev,
                                                  const float* __restrict__ W,
                                                  const float* __restrict__ asrc,
                                                  const float* __restrict__ adst) {
    __shared__ float sm[12288];                 // 48KB, aliased
    float (*As)[64]  = (float(*)[64])sm;        // [64][64]
    float (*Ws)[256] = (float(*)[256])(sm + 4096); // [32][256]
    int rowBase = blockIdx.x * 64;
    int tid = threadIdx.x;

    if (bgPrev == nullptr) {
        const float4* X4 = (const float4*)(g_X0 + (size_t)rowBase * 64);
#pragma unroll
        for (int q = 0; q < 4; q++) {
            int idx = tid + q * 256;
            int r = idx & 63, k4 = idx >> 6;
            float4 v = X4[r * 16 + k4];
            As[k4 * 4 + 0][r] = v.x;
            As[k4 * 4 + 1][r] = v.y;
            As[k4 * 4 + 2][r] = v.z;
            As[k4 * 4 + 3][r] = v.w;
        }
    } else {
#pragma unroll
        for (int q = 0; q < 4; q++) {
            int idx = tid + q * 256;
            int r = idx & 63, c = (idx >> 6) * 4;    // c in {0,4,...,60}
            size_t rg = (size_t)(rowBase + r) * 16 + (c & 15);
            float4 v = make_float4(0.f, 0.f, 0.f, 0.f);
#pragma unroll
            for (int h = 0; h < HEADS; h++) {
                float4 t = *(const float4*)&g_H[(size_t)(h * 4 + (c >> 4)) * HSLICE + rg];
                v.x += t.x; v.y += t.y; v.z += t.z; v.w += t.w;
            }
            float e0 = 0.25f * v.x + bgPrev[c];
            float e1 = 0.25f * v.y + bgPrev[c + 1];
            float e2 = 0.25f * v.z + bgPrev[c + 2];
            float e3 = 0.25f * v.w + bgPrev[c + 3];
            As[c + 0][r] = e0 > 0.f ? e0 : expm1f(e0);
            As[c + 1][r] = e1 > 0.f ? e1 : expm1f(e1);
            As[c + 2][r] = e2 > 0.f ? e2 : expm1f(e2);
            As[c + 3][r] = e3 > 0.f ? e3 : expm1f(e3);
        }
    }

    int lane = tid & 31, w = tid >> 5;
    int ry2 = lane >> 2, cx2 = lane & 3;
    int cg = w * 4 + cx2;                       // 0..31
    float acc[8][8] = {};
    const float4* W4 = (const float4*)W;

#pragma unroll
    for (int half = 0; half < 2; half++) {
        __syncthreads();
#pragma unroll
        for (int q = 0; q < 8; q++) {
            int idx = tid + q * 256;
            ((float4*)Ws)[idx] = W4[half * 2048 + idx];
        }
        __syncthreads();
#pragma unroll
        for (int kk = 0; kk < 32; kk++) {
            int k = half * 32 + kk;
            float4 a0 = *(const float4*)&As[k][ry2 * 4];
            float4 a1 = *(const float4*)&As[k][32 + ry2 * 4];
            float4 b0 = *(const float4*)&Ws[kk][cg * 4];
            float4 b1 = *(const float4*)&Ws[kk][128 + cg * 4];
            float av[8] = {a0.x, a0.y, a0.z, a0.w, a1.x, a1.y, a1.z, a1.w};
            float bv[8] = {b0.x, b0.y, b0.z, b0.w, b1.x, b1.y, b1.z, b1.w};
#pragma unroll
            for (int i = 0; i < 8; i++)
#pragma unroll
                for (int j = 0; j < 8; j++)
                    acc[i][j] += av[i] * bv[j];
        }
    }
    // store H in slice-major layout
    {
        int slLo = cg >> 2, slHi = 8 + (cg >> 2);
        int chB = (cg & 3) * 4;
#pragma unroll
        for (int i = 0; i < 8; i++) {
            int r = rowBase + ((i < 4) ? (ry2 * 4 + i) : (32 + ry2 * 4 + (i - 4)));
            *(float4*)&g_H[(size_t)slLo * HSLICE + r * 16 + chB] =
                make_float4(acc[i][0], acc[i][1], acc[i][2], acc[i][3]);
            *(float4*)&g_H[(size_t)slHi * HSLICE + r * 16 + chB] =
                make_float4(acc[i][4], acc[i][5], acc[i][6], acc[i][7]);
        }
    }

    // ---- fused ls/ld epilogue ----
    __syncthreads();                            // done reading As/Ws
    float (*redls)[4][16] = (float(*)[4][16])sm;          // [64][4][16]
    float (*redld)[4][16] = (float(*)[4][16])(sm + 4096);
    float as_lo[4], as_hi[4], ad_lo[4], ad_hi[4];
#pragma unroll
    for (int j = 0; j < 4; j++) {
        as_lo[j] = asrc[cg * 4 + j];
        as_hi[j] = asrc[128 + cg * 4 + j];
        ad_lo[j] = adst[cg * 4 + j];
        ad_hi[j] = adst[128 + cg * 4 + j];
    }
    int hA = cg >> 4;                           // head of low half (0/1)
    int slot = (w & 3) * 4 + cx2;               // 0..15
#pragma unroll
    for (int i = 0; i < 8; i++) {
        int r = (i < 4) ? (ry2 * 4 + i) : (32 + ry2 * 4 + (i - 4));
        float pls0 = 0, pls1 = 0, pld0 = 0, pld1 = 0;
#pragma unroll
        for (int j = 0; j < 4; j++) {
            pls0 += acc[i][j] * as_lo[j];
            pls1 += acc[i][4 + j] * as_hi[j];
            pld0 += acc[i][j] * ad_lo[j];
            pld1 += acc[i][4 + j] * ad_hi[j];
        }
        redls[r][hA][slot] = pls0;
        redls[r][2 + hA][slot] = pls1;
        redld[r][hA][slot] = pld0;
        redld[r][2 + hA][slot] = pld1;
    }
    __syncthreads();
    {
        int r = tid >> 2, h = tid & 3;
        float s = 0, d = 0;
#pragma unroll
        for (int k = 0; k < 16; k++) { s += redls[r][h][k]; d += redld[r][h][k]; }
        g_ls[(rowBase + r) * 4 + h] = s;
        g_ld[(rowBase + r) * 4 + h] = d;
    }
}

// ---------------- GAT aggregate v6: fused softmax + all-smem SpMM ------------
// grid (GG, 8): sl2 covers slices {sl2*2, sl2*2+1}; head h = sl2>>1.
// 1024 threads = 32 warps. Phase A stages H (128KB), srcList, ls/ld.
// Phase W computes normalized edge weights in smem (swv). Phase B is a pure
// LDS inner loop (swv/ssrc broadcast, Hs conflict-free by half-bank rotation).
__global__ void __launch_bounds__(1024) k_gat_agg6() {
    extern __shared__ float sm6[];
    float* Hs   = sm6;
    float* swv  = sm6 + AGG6_SWV;
    int*   ssrc = (int*)(sm6 + AGG6_SSRC);
    float* sls  = sm6 + AGG6_SLS;
    float* sld  = sm6 + AGG6_SLD;

    int g = blockIdx.x, sl2 = blockIdx.y;
    int sl0 = sl2 * 2;
    int h = sl2 >> 1;
    int tid = threadIdx.x;
    int lane = tid & 31, w = tid >> 5;
    size_t gb = (size_t)g * NN;
    float* __restrict__ H0 = g_H + (size_t)sl0 * HSLICE + gb * 16;
    float* __restrict__ H1 = g_H + (size_t)(sl0 + 1) * HSLICE + gb * 16;

    // Phase A: stage H slices, srcList, per-head ls/ld
    {
        const float4* s0 = (const float4*)H0;
        const float4* s1 = (const float4*)H1;
        float4* d0 = (float4*)Hs;
        float4* d1 = (float4*)(Hs + AGG6_HALF + AGG6_PAD);
        for (int idx = tid; idx < NN * 4; idx += 1024) {
            d0[idx] = s0[idx];
            d1[idx] = s1[idx];
        }
        for (int j = tid; j < EP; j += 1024)
            ssrc[j] = g_srcList[j];
        const float4* ls4 = (const float4*)(g_ls + gb * HEADS);
        const float4* ld4 = (const float4*)(g_ld + gb * HEADS);
        for (int n = tid; n < NN; n += 1024) {
            float4 a = ls4[n];
            float4 b = ld4[n];
            sls[n] = ((const float*)&a)[h];
            sld[n] = ((const float*)&b)[h];
        }
    }
    __syncthreads();

    // Phase W: thread-per-node softmax weights into swv (normalized in smem)
    for (int n = tid; n < NN; n += 1024) {
        int s0 = g_off[n], s1 = g_off[n + 1];
        float ldv = sld[n];
        float sum = 0.f;
        for (int j = s0; j < s1; j++) {
            float v = sls[ssrc[j]] + ldv;
            v = v > 0.f ? v : 0.2f * v;
            float wv = __expf(v);
            swv[j] = wv;
            sum += wv;
        }
        float inv = 1.f / (sum + 1e-16f);
        for (int j = s0; j < s1; j++)
            swv[j] *= inv;
    }
    __syncthreads();

    int chOff = (lane >> 4) * (AGG6_HALF + AGG6_PAD) + (lane & 15);
    float* __restrict__ Hout = ((lane < 16) ? H0 : H1) + (lane & 15);

    // Phase B: warp per node; pure-LDS inner loop serving 32 channels
    for (int n = w; n < NN; n += 32) {
        int s0 = g_off[n], s1 = g_off[n + 1];
        float acc = 0.f;
        int j = s0;
        for (; j + 2 <= s1; j += 2) {
            float a0 = swv[j],  a1 = swv[j + 1];
            int   i0 = ssrc[j], i1 = ssrc[j + 1];
            acc += a0 * Hs[i0 * 16 + chOff] + a1 * Hs[i1 * 16 + chOff];
        }
        if (j < s1)
            acc += swv[j] * Hs[ssrc[j] * 16 + chOff];
        Hout[n * 16] = acc;                     // in-place, 2x64B per warp
    }
}

// ---------------- head mean + bias + elu -> X1 (final layer only) ------------
__global__ void k_finish(const float* __restrict__ bg_l) {
    int tid = threadIdx.x;
    int r = blockIdx.x * 4 + (tid >> 6);
    int c = tid & 63;
    float v = 0.f;
#pragma unroll
    for (int h = 0; h < HEADS; h++) {
        int cc = h * 64 + c;
        v += g_H[(size_t)(cc >> 4) * HSLICE + (size_t)r * 16 + (cc & 15)];
    }
    v = 0.25f * v + bg_l[c];
    v = v > 0.f ? v : expm1f(v);
    g_X1[(size_t)r * 64 + c] = v;
}

// ---------------- GI split-K GEMM -------------------------------------------
__global__ void __launch_bounds__(256) k_gi_gemm(const float* __restrict__ Wih) {
    __shared__ float As[64][33];
    __shared__ float Ws[64][33];
    int kBase = blockIdx.x * KCH;
    int gateBase = blockIdx.y * 64;
    int tid = threadIdx.x;
    int tx = tid & 15, ty = tid >> 4;
    float acc[4][4] = {};
    for (int kt = 0; kt < KCH / 32; kt++) {
        int k0 = kBase + kt * 32;
#pragma unroll
        for (int i = 0; i < 8; i++) {
            int idx = tid + i * 256;
            int r = idx >> 5, kk = idx & 31;
            As[r][kk] = g_X1[r * NH + k0 + kk];
            Ws[r][kk] = Wih[(size_t)(gateBase + r) * NH + k0 + kk];
        }
        __syncthreads();
#pragma unroll
        for (int kk = 0; kk < 32; kk++) {
            float a[4], wv[4];
#pragma unroll
            for (int i = 0; i < 4; i++) a[i] = As[ty * 4 + i][kk];
#pragma unroll
            for (int j = 0; j < 4; j++) wv[j] = Ws[tx * 4 + j][kk];
#pragma unroll
            for (int i = 0; i < 4; i++)
#pragma unroll
                for (int j = 0; j < 4; j++)
                    acc[i][j] += a[i] * wv[j];
        }
        __syncthreads();
    }
#pragma unroll
    for (int i = 0; i < 4; i++)
#pragma unroll
        for (int j = 0; j < 4; j++)
            g_GIpart[(blockIdx.x * GG + ty * 4 + i) * GATES + gateBase + tx * 4 + j] = acc[i][j];
}

__global__ void k_gi_reduce(const float* __restrict__ b_ih) {
    int idx = blockIdx.x * blockDim.x + threadIdx.x;
    int j = idx % GATES;
    float s = b_ih[j];
    for (int kc = 0; kc < NCHUNK; kc++)
        s += g_GIpart[kc * GG * GATES + idx];
    g_GI[idx] = s;
}

// ---------------- GRU recurrence ----------------
__global__ void __launch_bounds__(256) k_gru(const float* __restrict__ Whh,
                                             const float* __restrict__ bhh) {
    __shared__ float h[BB][HID];
    __shared__ float gh[BB][GATES];
    int tid = threadIdx.x;
    h[tid >> 6][tid & 63] = 0.f;
    __syncthreads();
    for (int t = 0; t < TT; t++) {
#pragma unroll
        for (int q = 0; q < 3; q++) {
            int idx = tid + q * 256;
            int b = idx / GATES, j = idx % GATES;
            float s = bhh[j];
#pragma unroll
            for (int c = 0; c < HID; c++)
                s += h[b][c] * Whh[j * HID + c];
            gh[b][j] = s;
        }
        __syncthreads();
        int b = tid >> 6, c = tid & 63;
        int g = b * TT + t;
        float ir = g_GI[g * GATES + c]        + gh[b][c];
        float iz = g_GI[g * GATES + 64 + c]   + gh[b][64 + c];
        float in = g_GI[g * GATES + 128 + c];
        float hn = gh[b][128 + c];
        float r = 1.f / (1.f + expf(-ir));
        float z = 1.f / (1.f + expf(-iz));
        float nn = tanhf(in + r * hn);
        float hnew = (1.f - z) * nn + z * h[b][c];
        __syncthreads();
        h[b][c] = hnew;
        __syncthreads();
    }
    g_hT[tid] = h[tid >> 6][tid & 63];
}

// ---------------- final FC ----------------
__global__ void k_fc(const float* __restrict__ Wfc, const float* __restrict__ bfc,
                     float* __restrict__ out) {
    int b = blockIdx.x;
    int n = blockIdx.y * 256 + threadIdx.x;
    if (n >= NN) return;
    float s = bfc[n];
#pragma unroll
    for (int c = 0; c < HID; c++)
        s += g_hT[b * HID + c] * Wfc[c * NN + n];
    out[b * NN + n] = s;
}

// ---------------- launcher ----------------
extern "C" void kernel_launch(void* const* d_in, const int* in_sizes, int n_in,
                              void* d_out, int out_size) {
    const float* x_seq = (const float*)d_in[0];
    const int*   edge_index = (const int*)d_in[1];
    const float* W_in = (const float*)d_in[3];
    const float* b_in = (const float*)d_in[4];
    const float* Wg   = (const float*)d_in[5];
    const float* a_src= (const float*)d_in[6];
    const float* a_dst= (const float*)d_in[7];
    const float* bg   = (const float*)d_in[8];
    const float* W_ih = (const float*)d_in[9];
    const float* W_hh = (const float*)d_in[10];
    const float* b_ih = (const float*)d_in[11];
    const float* b_hh = (const float*)d_in[12];
    const float* W_fc = (const float*)d_in[13];
    const float* b_fc = (const float*)d_in[14];
    float* out = (float*)d_out;

    cudaFuncSetAttribute(k_gat_agg6,
                         cudaFuncAttributeMaxDynamicSharedMemorySize, AGG6_SMEM);

    // launches 1-3; #4 = layer-0 agg6 (ncu slot)
    k_csr_all<<<1, 1024>>>(edge_index);
    k_input_fc<<<RR / 4, 256>>>(x_seq, W_in, b_in);

    for (int l = 0; l < LL; l++) {
        const float* bgPrev = (l == 0) ? nullptr : (bg + (size_t)(l - 1) * HID);
        k_gat_gemm<<<RR / 64, 256>>>(bgPrev, Wg + (size_t)l * HID * 256,
                                     a_src + (size_t)l * HEADS * HID,
                                     a_dst + (size_t)l * HEADS * HID);
        k_gat_agg6<<<dim3(GG, 8), 1024, AGG6_SMEM>>>();
    }
    // layer-4 aggregated H -> X1 for the GRU input GEMM
    k_finish<<<RR / 4, 256>>>(bg + (size_t)(LL - 1) * HID);

    k_gi_gemm<<<dim3(NCHUNK, 3), 256>>>(W_ih);
    k_gi_reduce<<<(GG * GATES) / 256, 256>>>(b_ih);
    k_gru<<<1, 256>>>(W_hh, b_hh);
    k_fc<<<dim3(BB, 4), 256>>>(W_fc, b_fc, out);
}

// round 13
// speedup vs baseline: 1.3304x; 1.0122x over previous
#include <cuda_runtime.h>
#include <cuda_bf16.h>

// ---------------- problem constants ----------------
#define BB   4
#define TT   16
#define NN   1000
#define FIN  8
#define EE   8000
#define EP   9000          // edges + self loops
#define HID  64
#define HEADS 4
#define LL   5
#define GG   64            // B*T graphs
#define RR   64000         // G*N rows
#define NH   64000         // N*HID
#define GATES 192
#define KCH  512
#define NCHUNK 125

// H layout: slice-major. Column c of row r lives at
//   g_H[(c>>4) * (RR*16) + r*16 + (c&15)]
#define HSLICE (RR * 16)

// agg7 smem layout (floats):
//   Hs0[16000] | pad 16 | Hs1[16000] | srec[9000 float2] | sls[1000] | sld[1000]
#define AGG7_PAD    16
#define AGG7_HALF   (NN * 16)
#define AGG7_SREC   (2 * AGG7_HALF + AGG7_PAD)            // 32016 (8B aligned)
#define AGG7_SLS    (AGG7_SREC + 2 * EP)                  // 50016
#define AGG7_SLD    (AGG7_SLS + NN)                       // 51016
#define AGG7_SMEM   ((AGG7_SLD + NN) * 4)                 // 208064 B

// ---------------- device scratch ----------------
__device__ float g_X0[RR * HID];
__device__ float g_X1[RR * HID];
__device__ float g_H [16 * HSLICE];
__device__ float g_ls[RR * HEADS];
__device__ float g_ld[RR * HEADS];
__device__ int   g_off[NN + 1];
__device__ int   g_srcList[EP];
__device__ int   g_eid[EP];
__device__ float g_GIpart[NCHUNK * GG * GATES];
__device__ float g_GI[GG * GATES];
__device__ float g_hT[BB * HID];

// ---------------- CSR build: ONE kernel, one block (deterministic) -----------
__global__ void __launch_bounds__(1024) k_csr_all(const int* __restrict__ edge_index) {
    __shared__ int scnt[1024];
    __shared__ int sscan[1024];
    __shared__ int scur[1024];
    int tid = threadIdx.x;
    scnt[tid] = 0;
    __syncthreads();
    for (int e = tid; e < EE; e += 1024)
        atomicAdd(&scnt[edge_index[EE + e]], 1);
    __syncthreads();
    int v = (tid < NN) ? (scnt[tid] + 1) : 0;    // +1 self loop
    sscan[tid] = v;
    __syncthreads();
    for (int o = 1; o < 1024; o <<= 1) {
        int add = (tid >= o) ? sscan[tid - o] : 0;
        __syncthreads();
        sscan[tid] += add;
        __syncthreads();
    }
    if (tid < NN) {
        g_off[tid + 1] = sscan[tid];
        scur[tid] = (tid == 0) ? 0 : sscan[tid - 1];
    }
    if (tid == 0) g_off[0] = 0;
    __syncthreads();
    for (int e = tid; e < EP; e += 1024) {
        int s, d;
        if (e < EE) { s = edge_index[e]; d = edge_index[EE + e]; }
        else        { s = e - EE;        d = e - EE; }
        int pos = atomicAdd(&scur[d], 1);
        g_srcList[pos] = s;
        g_eid[pos] = e;
    }
    __syncthreads();
    if (tid < NN) {                       // stable order by edge id
        int s0 = g_off[tid], s1 = g_off[tid + 1];
        for (int i = s0 + 1; i < s1; i++) {
            int id = g_eid[i], sv = g_srcList[i];
            int j = i - 1;
            while (j >= s0 && g_eid[j] > id) {
                g_eid[j + 1] = g_eid[j];
                g_srcList[j + 1] = g_srcList[j];
                j--;
            }
            g_eid[j + 1] = id;
            g_srcList[j + 1] = sv;
        }
    }
}

// ---------------- input projection ----------------
__global__ void k_input_fc(const float* __restrict__ x,
                           const float* __restrict__ W_in,
                           const float* __restrict__ b_in) {
    int tid = threadIdx.x;
    int r = blockIdx.x * 4 + (tid >> 6);
    int c = tid & 63;
    float s = b_in[c];
#pragma unroll
    for (int f = 0; f < FIN; f++)
        s += x[r * FIN + f] * W_in[f * HID + c];
    g_X0[r * HID + c] = s;
}

// ---------------- GAT GEMM + fused finish + fused ls/ld epilogue -------------
// bgPrev == nullptr: As from g_X0 (layer 0).
// else: As[k][r] = elu(0.25 * sum_h H_agg[r][h*64+k] + bgPrev[k])
__global__ void __launch_bounds__(256) k_gat_gemm(const float* __restrict__ bgPrev,
                                                  const float* __restrict__ W,
                                                  const float* __restrict__ asrc,
                                                  const float* __restrict__ adst) {
    __shared__ float sm[12288];                 // 48KB, aliased
    float (*As)[64]  = (float(*)[64])sm;        // [64][64]
    float (*Ws)[256] = (float(*)[256])(sm + 4096); // [32][256]
    int rowBase = blockIdx.x * 64;
    int tid = threadIdx.x;

    if (bgPrev == nullptr) {
        const float4* X4 = (const float4*)(g_X0 + (size_t)rowBase * 64);
#pragma unroll
        for (int q = 0; q < 4; q++) {
            int idx = tid + q * 256;
            int r = idx & 63, k4 = idx >> 6;
            float4 v = X4[r * 16 + k4];
            As[k4 * 4 + 0][r] = v.x;
            As[k4 * 4 + 1][r] = v.y;
            As[k4 * 4 + 2][r] = v.z;
            As[k4 * 4 + 3][r] = v.w;
        }
    } else {
#pragma unroll
        for (int q = 0; q < 4; q++) {
            int idx = tid + q * 256;
            int r = idx & 63, c = (idx >> 6) * 4;    // c in {0,4,...,60}
            size_t rg = (size_t)(rowBase + r) * 16 + (c & 15);
            float4 v = make_float4(0.f, 0.f, 0.f, 0.f);
#pragma unroll
            for (int h = 0; h < HEADS; h++) {
                float4 t = *(const float4*)&g_H[(size_t)(h * 4 + (c >> 4)) * HSLICE + rg];
                v.x += t.x; v.y += t.y; v.z += t.z; v.w += t.w;
            }
            float e0 = 0.25f * v.x + bgPrev[c];
            float e1 = 0.25f * v.y + bgPrev[c + 1];
            float e2 = 0.25f * v.z + bgPrev[c + 2];
            float e3 = 0.25f * v.w + bgPrev[c + 3];
            As[c + 0][r] = e0 > 0.f ? e0 : expm1f(e0);
            As[c + 1][r] = e1 > 0.f ? e1 : expm1f(e1);
            As[c + 2][r] = e2 > 0.f ? e2 : expm1f(e2);
            As[c + 3][r] = e3 > 0.f ? e3 : expm1f(e3);
        }
    }

    int lane = tid & 31, w = tid >> 5;
    int ry2 = lane >> 2, cx2 = lane & 3;
    int cg = w * 4 + cx2;                       // 0..31
    float acc[8][8] = {};
    const float4* W4 = (const float4*)W;

#pragma unroll
    for (int half = 0; half < 2; half++) {
        __syncthreads();
#pragma unroll
        for (int q = 0; q < 8; q++) {
            int idx = tid + q * 256;
            ((float4*)Ws)[idx] = W4[half * 2048 + idx];
        }
        __syncthreads();
#pragma unroll
        for (int kk = 0; kk < 32; kk++) {
            int k = half * 32 + kk;
            float4 a0 = *(const float4*)&As[k][ry2 * 4];
            float4 a1 = *(const float4*)&As[k][32 + ry2 * 4];
            float4 b0 = *(const float4*)&Ws[kk][cg * 4];
            float4 b1 = *(const float4*)&Ws[kk][128 + cg * 4];
            float av[8] = {a0.x, a0.y, a0.z, a0.w, a1.x, a1.y, a1.z, a1.w};
            float bv[8] = {b0.x, b0.y, b0.z, b0.w, b1.x, b1.y, b1.z, b1.w};
#pragma unroll
            for (int i = 0; i < 8; i++)
#pragma unroll
                for (int j = 0; j < 8; j++)
                    acc[i][j] += av[i] * bv[j];
        }
    }
    // store H in slice-major layout
    {
        int slLo = cg >> 2, slHi = 8 + (cg >> 2);
        int chB = (cg & 3) * 4;
#pragma unroll
        for (int i = 0; i < 8; i++) {
            int r = rowBase + ((i < 4) ? (ry2 * 4 + i) : (32 + ry2 * 4 + (i - 4)));
            *(float4*)&g_H[(size_t)slLo * HSLICE + r * 16 + chB] =
                make_float4(acc[i][0], acc[i][1], acc[i][2], acc[i][3]);
            *(float4*)&g_H[(size_t)slHi * HSLICE + r * 16 + chB] =
                make_float4(acc[i][4], acc[i][5], acc[i][6], acc[i][7]);
        }
    }

    // ---- fused ls/ld epilogue ----
    __syncthreads();                            // done reading As/Ws
    float (*redls)[4][16] = (float(*)[4][16])sm;          // [64][4][16]
    float (*redld)[4][16] = (float(*)[4][16])(sm + 4096);
    float as_lo[4], as_hi[4], ad_lo[4], ad_hi[4];
#pragma unroll
    for (int j = 0; j < 4; j++) {
        as_lo[j] = asrc[cg * 4 + j];
        as_hi[j] = asrc[128 + cg * 4 + j];
        ad_lo[j] = adst[cg * 4 + j];
        ad_hi[j] = adst[128 + cg * 4 + j];
    }
    int hA = cg >> 4;                           // head of low half (0/1)
    int slot = (w & 3) * 4 + cx2;               // 0..15
#pragma unroll
    for (int i = 0; i < 8; i++) {
        int r = (i < 4) ? (ry2 * 4 + i) : (32 + ry2 * 4 + (i - 4));
        float pls0 = 0, pls1 = 0, pld0 = 0, pld1 = 0;
#pragma unroll
        for (int j = 0; j < 4; j++) {
            pls0 += acc[i][j] * as_lo[j];
            pls1 += acc[i][4 + j] * as_hi[j];
            pld0 += acc[i][j] * ad_lo[j];
            pld1 += acc[i][4 + j] * ad_hi[j];
        }
        redls[r][hA][slot] = pls0;
        redls[r][2 + hA][slot] = pls1;
        redld[r][hA][slot] = pld0;
        redld[r][2 + hA][slot] = pld1;
    }
    __syncthreads();
    {
        int r = tid >> 2, h = tid & 3;
        float s = 0, d = 0;
#pragma unroll
        for (int k = 0; k < 16; k++) { s += redls[r][h][k]; d += redld[r][h][k]; }
        g_ls[(rowBase + r) * 4 + h] = s;
        g_ld[(rowBase + r) * 4 + h] = d;
    }
}

// ---------------- GAT aggregate v7: float2 records + float2 channels ---------
// grid (GG, 8): sl2 covers slices {sl2*2, sl2*2+1}; head h = sl2>>1.
// 1024 threads = 32 warps, warp-per-node.
// Lane roles: eh = lane>>4 selects even/odd edges; ch2 = lane&15 selects a
// channel PAIR (ch2 0-7 -> slice0, 8-15 -> slice1 via pad rotation).
// Inner loop: LDS.64 record (alpha, src*16) + LDS.64 Hs pair + 2 FFMA.
__global__ void __launch_bounds__(1024) k_gat_agg7() {
    extern __shared__ float sm7[];
    float*  Hs   = sm7;
    float2* srec = (float2*)(sm7 + AGG7_SREC);
    float*  sls  = sm7 + AGG7_SLS;
    float*  sld  = sm7 + AGG7_SLD;

    int g = blockIdx.x, sl2 = blockIdx.y;
    int sl0 = sl2 * 2;
    int h = sl2 >> 1;
    int tid = threadIdx.x;
    int lane = tid & 31, w = tid >> 5;
    size_t gb = (size_t)g * NN;
    float* __restrict__ H0 = g_H + (size_t)sl0 * HSLICE + gb * 16;
    float* __restrict__ H1 = g_H + (size_t)(sl0 + 1) * HSLICE + gb * 16;

    // Phase A: stage H slices, edge records (src only), per-head ls/ld
    {
        const float4* s0 = (const float4*)H0;
        const float4* s1 = (const float4*)H1;
        float4* d0 = (float4*)Hs;
        float4* d1 = (float4*)(Hs + AGG7_HALF + AGG7_PAD);
        for (int idx = tid; idx < NN * 4; idx += 1024) {
            d0[idx] = s0[idx];
            d1[idx] = s1[idx];
        }
        for (int j = tid; j < EP; j += 1024)
            srec[j].y = __int_as_float(g_srcList[j] * 16);
        const float4* ls4 = (const float4*)(g_ls + gb * HEADS);
        const float4* ld4 = (const float4*)(g_ld + gb * HEADS);
        for (int n = tid; n < NN; n += 1024) {
            float4 a = ls4[n];
            float4 b = ld4[n];
            sls[n] = ((const float*)&a)[h];
            sld[n] = ((const float*)&b)[h];
        }
    }
    __syncthreads();

    // Phase W: thread-per-node normalized softmax weights into srec.x
    for (int n = tid; n < NN; n += 1024) {
        int s0 = g_off[n], s1 = g_off[n + 1];
        float ldv = sld[n];
        float sum = 0.f;
        for (int j = s0; j < s1; j++) {
            int s = __float_as_int(srec[j].y) >> 4;
            float v = sls[s] + ldv;
            v = v > 0.f ? v : 0.2f * v;
            float wv = __expf(v);
            srec[j].x = wv;
            sum += wv;
        }
        float inv = 1.f / (sum + 1e-16f);
        for (int j = s0; j < s1; j++)
            srec[j].x *= inv;
    }
    __syncthreads();

    int eh  = lane >> 4;                        // edge parity half
    int ch2 = lane & 15;                        // channel-pair index
    int chOff2 = (ch2 >> 3) * (AGG7_HALF + AGG7_PAD) + (ch2 & 7) * 2;
    float* __restrict__ Hout = ((ch2 < 8) ? H0 : H1) + (ch2 & 7) * 2;

    // Phase B: warp per node; each lane = (edge parity, channel pair)
    for (int n = w; n < NN; n += 32) {
        int s0 = g_off[n], s1 = g_off[n + 1];
        float ax = 0.f, ay = 0.f;
        int j = s0 + eh;
        for (; j + 2 < s1; j += 4) {            // 2 records in flight per half
            float2 r0 = srec[j];
            float2 r1 = srec[j + 2];
            const float2 h0 = *(const float2*)&Hs[__float_as_int(r0.y) + chOff2];
            const float2 h1 = *(const float2*)&Hs[__float_as_int(r1.y) + chOff2];
            ax += r0.x * h0.x + r1.x * h1.x;
            ay += r0.x * h0.y + r1.x * h1.y;
        }
        if (j < s1) {
            float2 r0 = srec[j];
            const float2 h0 = *(const float2*)&Hs[__float_as_int(r0.y) + chOff2];
            ax += r0.x * h0.x;
            ay += r0.x * h0.y;
        }
        ax += __shfl_down_sync(0xffffffffu, ax, 16);
        ay += __shfl_down_sync(0xffffffffu, ay, 16);
        if (eh == 0)
            *(float2*)&Hout[n * 16] = make_float2(ax, ay);   // in-place
    }
}

// ---------------- head mean + bias + elu -> X1 (final layer only) ------------
__global__ void k_finish(const float* __restrict__ bg_l) {
    int tid = threadIdx.x;
    int r = blockIdx.x * 4 + (tid >> 6);
    int c = tid & 63;
    float v = 0.f;
#pragma unroll
    for (int h = 0; h < HEADS; h++) {
        int cc = h * 64 + c;
        v += g_H[(size_t)(cc >> 4) * HSLICE + (size_t)r * 16 + (cc & 15)];
    }
    v = 0.25f * v + bg_l[c];
    v = v > 0.f ? v : expm1f(v);
    g_X1[(size_t)r * 64 + c] = v;
}

// ---------------- GI split-K GEMM -------------------------------------------
__global__ void __launch_bounds__(256) k_gi_gemm(const float* __restrict__ Wih) {
    __shared__ float As[64][33];
    __shared__ float Ws[64][33];
    int kBase = blockIdx.x * KCH;
    int gateBase = blockIdx.y * 64;
    int tid = threadIdx.x;
    int tx = tid & 15, ty = tid >> 4;
    float acc[4][4] = {};
    for (int kt = 0; kt < KCH / 32; kt++) {
        int k0 = kBase + kt * 32;
#pragma unroll
        for (int i = 0; i < 8; i++) {
            int idx = tid + i * 256;
            int r = idx >> 5, kk = idx & 31;
            As[r][kk] = g_X1[r * NH + k0 + kk];
            Ws[r][kk] = Wih[(size_t)(gateBase + r) * NH + k0 + kk];
        }
        __syncthreads();
#pragma unroll
        for (int kk = 0; kk < 32; kk++) {
            float a[4], wv[4];
#pragma unroll
            for (int i = 0; i < 4; i++) a[i] = As[ty * 4 + i][kk];
#pragma unroll
            for (int j = 0; j < 4; j++) wv[j] = Ws[tx * 4 + j][kk];
#pragma unroll
            for (int i = 0; i < 4; i++)
#pragma unroll
                for (int j = 0; j < 4; j++)
                    acc[i][j] += a[i] * wv[j];
        }
        __syncthreads();
    }
#pragma unroll
    for (int i = 0; i < 4; i++)
#pragma unroll
        for (int j = 0; j < 4; j++)
            g_GIpart[(blockIdx.x * GG + ty * 4 + i) * GATES + gateBase + tx * 4 + j] = acc[i][j];
}

__global__ void k_gi_reduce(const float* __restrict__ b_ih) {
    int idx = blockIdx.x * blockDim.x + threadIdx.x;
    int j = idx % GATES;
    float s = b_ih[j];
    for (int kc = 0; kc < NCHUNK; kc++)
        s += g_GIpart[kc * GG * GATES + idx];
    g_GI[idx] = s;
}

// ---------------- GRU recurrence ----------------
__global__ void __launch_bounds__(256) k_gru(const float* __restrict__ Whh,
                                             const float* __restrict__ bhh) {
    __shared__ float h[BB][HID];
    __shared__ float gh[BB][GATES];
    int tid = threadIdx.x;
    h[tid >> 6][tid & 63] = 0.f;
    __syncthreads();
    for (int t = 0; t < TT; t++) {
#pragma unroll
        for (int q = 0; q < 3; q++) {
            int idx = tid + q * 256;
            int b = idx / GATES, j = idx % GATES;
            float s = bhh[j];
#pragma unroll
            for (int c = 0; c < HID; c++)
                s += h[b][c] * Whh[j * HID + c];
            gh[b][j] = s;
        }
        __syncthreads();
        int b = tid >> 6, c = tid & 63;
        int g = b * TT + t;
        float ir = g_GI[g * GATES + c]        + gh[b][c];
        float iz = g_GI[g * GATES + 64 + c]   + gh[b][64 + c];
        float in = g_GI[g * GATES + 128 + c];
        float hn = gh[b][128 + c];
        float r = 1.f / (1.f + expf(-ir));
        float z = 1.f / (1.f + expf(-iz));
        float nn = tanhf(in + r * hn);
        float hnew = (1.f - z) * nn + z * h[b][c];
        __syncthreads();
        h[b][c] = hnew;
        __syncthreads();
    }
    g_hT[tid] = h[tid >> 6][tid & 63];
}

// ---------------- final FC ----------------
__global__ void k_fc(const float* __restrict__ Wfc, const float* __restrict__ bfc,
                     float* __restrict__ out) {
    int b = blockIdx.x;
    int n = blockIdx.y * 256 + threadIdx.x;
    if (n >= NN) return;
    float s = bfc[n];
#pragma unroll
    for (int c = 0; c < HID; c++)
        s += g_hT[b * HID + c] * Wfc[c * NN + n];
    out[b * NN + n] = s;
}

// ---------------- launcher ----------------
extern "C" void kernel_launch(void* const* d_in, const int* in_sizes, int n_in,
                              void* d_out, int out_size) {
    const float* x_seq = (const float*)d_in[0];
    const int*   edge_index = (const int*)d_in[1];
    const float* W_in = (const float*)d_in[3];
    const float* b_in = (const float*)d_in[4];
    const float* Wg   = (const float*)d_in[5];
    const float* a_src= (const float*)d_in[6];
    const float* a_dst= (const float*)d_in[7];
    const float* bg   = (const float*)d_in[8];
    const float* W_ih = (const float*)d_in[9];
    const float* W_hh = (const float*)d_in[10];
    const float* b_ih = (const float*)d_in[11];
    const float* b_hh = (const float*)d_in[12];
    const float* W_fc = (const float*)d_in[13];
    const float* b_fc = (const float*)d_in[14];
    float* out = (float*)d_out;

    cudaFuncSetAttribute(k_gat_agg7,
                         cudaFuncAttributeMaxDynamicSharedMemorySize, AGG7_SMEM);

    // launches 1-3; #4 = layer-0 agg7 (ncu slot)
    k_csr_all<<<1, 1024>>>(edge_index);
    k_input_fc<<<RR / 4, 256>>>(x_seq, W_in, b_in);

    for (int l = 0; l < LL; l++) {
        const float* bgPrev = (l == 0) ? nullptr : (bg + (size_t)(l - 1) * HID);
        k_gat_gemm<<<RR / 64, 256>>>(bgPrev, Wg + (size_t)l * HID * 256,
                                     a_src + (size_t)l * HEADS * HID,
                                     a_dst + (size_t)l * HEADS * HID);
        k_gat_agg7<<<dim3(GG, 8), 1024, AGG7_SMEM>>>();
    }
    // layer-4 aggregated H -> X1 for the GRU input GEMM
    k_finish<<<RR / 4, 256>>>(bg + (size_t)(LL - 1) * HID);

    k_gi_gemm<<<dim3(NCHUNK, 3), 256>>>(W_ih);
    k_gi_reduce<<<(GG * GATES) / 256, 256>>>(b_ih);
    k_gru<<<1, 256>>>(W_hh, b_hh);
    k_fc<<<dim3(BB, 4), 256>>>(W_fc, b_fc, out);
}

// round 15
// speedup vs baseline: 1.3983x; 1.0510x over previous
#include <cuda_runtime.h>
#include <cuda_bf16.h>

// ---------------- problem constants ----------------
#define BB   4
#define TT   16
#define NN   1000
#define FIN  8
#define EE   8000
#define EP   9000          // edges + self loops
#define HID  64
#define HEADS 4
#define LL   5
#define GG   64            // B*T graphs
#define RR   64000         // G*N rows
#define NH   64000         // N*HID
#define GATES 192
#define KCH  512
#define NCHUNK 125

// H layout: slice-major. Column c of row r lives at
//   g_H[(c>>4) * (RR*16) + r*16 + (c&15)]
#define HSLICE (RR * 16)

// agg7 smem layout (floats):
//   Hs0[16000] | pad 16 | Hs1[16000] | srec[9000 float2] | sls[1000] | sld[1000] | sgoff[1001]
#define AGG7_PAD    16
#define AGG7_HALF   (NN * 16)
#define AGG7_SREC   (2 * AGG7_HALF + AGG7_PAD)            // 32016 (8B aligned)
#define AGG7_SLS    (AGG7_SREC + 2 * EP)                  // 50016
#define AGG7_SLD    (AGG7_SLS + NN)                       // 51016
#define AGG7_SOFF   (AGG7_SLD + NN)                       // 52016
#define AGG7_SMEM   ((AGG7_SOFF + NN + 1) * 4)            // 212068 B

// ---- Blackwell packed fp32x2 FMA (2 IEEE fp32 FMAs per instruction) ----
#define FMA_F32X2(d, a, b, c) \
    asm("fma.rn.f32x2 %0, %1, %2, %3;" : "=l"(d) : "l"(a), "l"(b), "l"(c))
#define PACK_F32X2(out, lo, hi) \
    asm("mov.b64 %0, {%1, %2};" : "=l"(out) : "f"(lo), "f"(hi))
#define UNPACK_F32X2(lo, hi, in) \
    asm("mov.b64 {%0, %1}, %2;" : "=f"(lo), "=f"(hi) : "l"(in))

// ---------------- device scratch ----------------
__device__ float g_X0[RR * HID];
__device__ float g_X1[RR * HID];
__device__ float g_H [16 * HSLICE];
__device__ float g_ls[RR * HEADS];
__device__ float g_ld[RR * HEADS];
__device__ int   g_off[NN + 1];
__device__ int   g_srcList[EP];
__device__ int   g_eid[EP];
__device__ float g_GIpart[NCHUNK * GG * GATES];
__device__ float g_GI[GG * GATES];
__device__ float g_hT[BB * HID];

// ---------------- CSR build: ONE kernel, one block (deterministic) -----------
__global__ void __launch_bounds__(1024) k_csr_all(const int* __restrict__ edge_index) {
    __shared__ int scnt[1024];
    __shared__ int sscan[1024];
    __shared__ int scur[1024];
    int tid = threadIdx.x;
    scnt[tid] = 0;
    __syncthreads();
    for (int e = tid; e < EE; e += 1024)
        atomicAdd(&scnt[edge_index[EE + e]], 1);
    __syncthreads();
    int v = (tid < NN) ? (scnt[tid] + 1) : 0;    // +1 self loop
    sscan[tid] = v;
    __syncthreads();
    for (int o = 1; o < 1024; o <<= 1) {
        int add = (tid >= o) ? sscan[tid - o] : 0;
        __syncthreads();
        sscan[tid] += add;
        __syncthreads();
    }
    if (tid < NN) {
        g_off[tid + 1] = sscan[tid];
        scur[tid] = (tid == 0) ? 0 : sscan[tid - 1];
    }
    if (tid == 0) g_off[0] = 0;
    __syncthreads();
    for (int e = tid; e < EP; e += 1024) {
        int s, d;
        if (e < EE) { s = edge_index[e]; d = edge_index[EE + e]; }
        else        { s = e - EE;        d = e - EE; }
        int pos = atomicAdd(&scur[d], 1);
        g_srcList[pos] = s;
        g_eid[pos] = e;
    }
    __syncthreads();
    if (tid < NN) {                       // stable order by edge id
        int s0 = g_off[tid], s1 = g_off[tid + 1];
        for (int i = s0 + 1; i < s1; i++) {
            int id = g_eid[i], sv = g_srcList[i];
            int j = i - 1;
            while (j >= s0 && g_eid[j] > id) {
                g_eid[j + 1] = g_eid[j];
                g_srcList[j + 1] = g_srcList[j];
                j--;
            }
            g_eid[j + 1] = id;
            g_srcList[j + 1] = sv;
        }
    }
}

// ---------------- input projection (half grid per launch) ----------------
__global__ void k_input_fc(const float* __restrict__ x,
                           const float* __restrict__ W_in,
                           const float* __restrict__ b_in, int rowBase) {
    int tid = threadIdx.x;
    int r = rowBase + blockIdx.x * 4 + (tid >> 6);
    int c = tid & 63;
    float s = b_in[c];
#pragma unroll
    for (int f = 0; f < FIN; f++)
        s += x[r * FIN + f] * W_in[f * HID + c];
    g_X0[r * HID + c] = s;
}

// ---------------- GAT GEMM (f32x2) + fused finish + fused ls/ld epilogue -----
// bgPrev == nullptr: As from g_X0 (layer 0).
// else: As[k][r] = elu(0.25 * sum_h H_agg[r][h*64+k] + bgPrev[k])
__global__ void __launch_bounds__(256) k_gat_gemm(const float* __restrict__ bgPrev,
                                                  const float* __restrict__ W,
                                                  const float* __restrict__ asrc,
                                                  const float* __restrict__ adst) {
    __shared__ float sm[12288];                 // 48KB, aliased
    float (*As)[64]  = (float(*)[64])sm;        // [64][64]
    float (*Ws)[256] = (float(*)[256])(sm + 4096); // [32][256]
    int rowBase = blockIdx.x * 64;
    int tid = threadIdx.x;

    if (bgPrev == nullptr) {
        const float4* X4 = (const float4*)(g_X0 + (size_t)rowBase * 64);
#pragma unroll
        for (int q = 0; q < 4; q++) {
            int idx = tid + q * 256;
            int r = idx & 63, k4 = idx >> 6;
            float4 v = X4[r * 16 + k4];
            As[k4 * 4 + 0][r] = v.x;
            As[k4 * 4 + 1][r] = v.y;
            As[k4 * 4 + 2][r] = v.z;
            As[k4 * 4 + 3][r] = v.w;
        }
    } else {
#pragma unroll
        for (int q = 0; q < 4; q++) {
            int idx = tid + q * 256;
            int r = idx & 63, c = (idx >> 6) * 4;    // c in {0,4,...,60}
            size_t rg = (size_t)(rowBase + r) * 16 + (c & 15);
            float4 v = make_float4(0.f, 0.f, 0.f, 0.f);
#pragma unroll
            for (int h = 0; h < HEADS; h++) {
                float4 t = *(const float4*)&g_H[(size_t)(h * 4 + (c >> 4)) * HSLICE + rg];
                v.x += t.x; v.y += t.y; v.z += t.z; v.w += t.w;
            }
            float e0 = 0.25f * v.x + bgPrev[c];
            float e1 = 0.25f * v.y + bgPrev[c + 1];
            float e2 = 0.25f * v.z + bgPrev[c + 2];
            float e3 = 0.25f * v.w + bgPrev[c + 3];
            As[c + 0][r] = e0 > 0.f ? e0 : expm1f(e0);
            As[c + 1][r] = e1 > 0.f ? e1 : expm1f(e1);
            As[c + 2][r] = e2 > 0.f ? e2 : expm1f(e2);
            As[c + 3][r] = e3 > 0.f ? e3 : expm1f(e3);
        }
    }

    int lane = tid & 31, w = tid >> 5;
    int ry2 = lane >> 2, cx2 = lane & 3;
    int cg = w * 4 + cx2;                       // 0..31
    unsigned long long accP[8][4];              // acc pairs along j
#pragma unroll
    for (int i = 0; i < 8; i++)
#pragma unroll
        for (int jp = 0; jp < 4; jp++) accP[i][jp] = 0ull;
    const float4* W4 = (const float4*)W;

#pragma unroll
    for (int half = 0; half < 2; half++) {
        __syncthreads();
#pragma unroll
        for (int q = 0; q < 8; q++) {
            int idx = tid + q * 256;
            ((float4*)Ws)[idx] = W4[half * 2048 + idx];
        }
        __syncthreads();
#pragma unroll
        for (int kk = 0; kk < 32; kk++) {
            int k = half * 32 + kk;
            float4 a0 = *(const float4*)&As[k][ry2 * 4];
            float4 a1 = *(const float4*)&As[k][32 + ry2 * 4];
            // b pairs straight from smem (16B-aligned)
            ulonglong2 b0p = *(const ulonglong2*)&Ws[kk][cg * 4];
            ulonglong2 b1p = *(const ulonglong2*)&Ws[kk][128 + cg * 4];
            unsigned long long bP[4] = {b0p.x, b0p.y, b1p.x, b1p.y};
            float av[8] = {a0.x, a0.y, a0.z, a0.w, a1.x, a1.y, a1.z, a1.w};
#pragma unroll
            for (int i = 0; i < 8; i++) {
                unsigned long long aD;
                PACK_F32X2(aD, av[i], av[i]);
#pragma unroll
                for (int jp = 0; jp < 4; jp++)
                    FMA_F32X2(accP[i][jp], aD, bP[jp], accP[i][jp]);
            }
        }
    }
    // unpack to scalar acc for store + epilogue
    float acc[8][8];
#pragma unroll
    for (int i = 0; i < 8; i++)
#pragma unroll
        for (int jp = 0; jp < 4; jp++)
            UNPACK_F32X2(acc[i][jp * 2], acc[i][jp * 2 + 1], accP[i][jp]);

    // store H in slice-major layout
    {
        int slLo = cg >> 2, slHi = 8 + (cg >> 2);
        int chB = (cg & 3) * 4;
#pragma unroll
        for (int i = 0; i < 8; i++) {
            int r = rowBase + ((i < 4) ? (ry2 * 4 + i) : (32 + ry2 * 4 + (i - 4)));
            *(float4*)&g_H[(size_t)slLo * HSLICE + r * 16 + chB] =
                make_float4(acc[i][0], acc[i][1], acc[i][2], acc[i][3]);
            *(float4*)&g_H[(size_t)slHi * HSLICE + r * 16 + chB] =
                make_float4(acc[i][4], acc[i][5], acc[i][6], acc[i][7]);
        }
    }

    // ---- fused ls/ld epilogue ----
    __syncthreads();                            // done reading As/Ws
    float (*redls)[4][16] = (float(*)[4][16])sm;          // [64][4][16]
    float (*redld)[4][16] = (float(*)[4][16])(sm + 4096);
    float as_lo[4], as_hi[4], ad_lo[4], ad_hi[4];
#pragma unroll
    for (int j = 0; j < 4; j++) {
        as_lo[j] = asrc[cg * 4 + j];
        as_hi[j] = asrc[128 + cg * 4 + j];
        ad_lo[j] = adst[cg * 4 + j];
        ad_hi[j] = adst[128 + cg * 4 + j];
    }
    int hA = cg >> 4;                           // head of low half (0/1)
    int slot = (w & 3) * 4 + cx2;               // 0..15
#pragma unroll
    for (int i = 0; i < 8; i++) {
        int r = (i < 4) ? (ry2 * 4 + i) : (32 + ry2 * 4 + (i - 4));
        float pls0 = 0, pls1 = 0, pld0 = 0, pld1 = 0;
#pragma unroll
        for (int j = 0; j < 4; j++) {
            pls0 += acc[i][j] * as_lo[j];
            pls1 += acc[i][4 + j] * as_hi[j];
            pld0 += acc[i][j] * ad_lo[j];
            pld1 += acc[i][4 + j] * ad_hi[j];
        }
        redls[r][hA][slot] = pls0;
        redls[r][2 + hA][slot] = pls1;
        redld[r][hA][slot] = pld0;
        redld[r][2 + hA][slot] = pld1;
    }
    __syncthreads();
    {
        int r = tid >> 2, h = tid & 3;
        float s = 0, d = 0;
#pragma unroll
        for (int k = 0; k < 16; k++) { s += redls[r][h][k]; d += redld[r][h][k]; }
        g_ls[(rowBase + r) * 4 + h] = s;
        g_ld[(rowBase + r) * 4 + h] = d;
    }
}

// ---------------- GAT aggregate v7b: float2 records + smem g_off -------------
// grid (GG, 8): sl2 covers slices {sl2*2, sl2*2+1}; head h = sl2>>1.
__global__ void __launch_bounds__(1024) k_gat_agg7() {
    extern __shared__ float sm7[];
    float*  Hs   = sm7;
    float2* srec = (float2*)(sm7 + AGG7_SREC);
    float*  sls  = sm7 + AGG7_SLS;
    float*  sld  = sm7 + AGG7_SLD;
    int*    soff = (int*)(sm7 + AGG7_SOFF);

    int g = blockIdx.x, sl2 = blockIdx.y;
    int sl0 = sl2 * 2;
    int h = sl2 >> 1;
    int tid = threadIdx.x;
    int lane = tid & 31, w = tid >> 5;
    size_t gb = (size_t)g * NN;
    float* __restrict__ H0 = g_H + (size_t)sl0 * HSLICE + gb * 16;
    float* __restrict__ H1 = g_H + (size_t)(sl0 + 1) * HSLICE + gb * 16;

    // Phase A: stage H slices, edge records (src only), per-head ls/ld, g_off
    {
        const float4* s0 = (const float4*)H0;
        const float4* s1 = (const float4*)H1;
        float4* d0 = (float4*)Hs;
        float4* d1 = (float4*)(Hs + AGG7_HALF + AGG7_PAD);
        for (int idx = tid; idx < NN * 4; idx += 1024) {
            d0[idx] = s0[idx];
            d1[idx] = s1[idx];
        }
        for (int j = tid; j < EP; j += 1024)
            srec[j].y = __int_as_float(g_srcList[j] * 16);
        const float4* ls4 = (const float4*)(g_ls + gb * HEADS);
        const float4* ld4 = (const float4*)(g_ld + gb * HEADS);
        for (int n = tid; n < NN; n += 1024) {
            float4 a = ls4[n];
            float4 b = ld4[n];
            sls[n] = ((const float*)&a)[h];
            sld[n] = ((const float*)&b)[h];
        }
        for (int n = tid; n < NN + 1; n += 1024)
            soff[n] = g_off[n];
    }
    __syncthreads();

    // Phase W: thread-per-node normalized softmax weights into srec.x
    for (int n = tid; n < NN; n += 1024) {
        int s0 = soff[n], s1 = soff[n + 1];
        float ldv = sld[n];
        float sum = 0.f;
        for (int j = s0; j < s1; j++) {
            int s = __float_as_int(srec[j].y) >> 4;
            float v = sls[s] + ldv;
            v = v > 0.f ? v : 0.2f * v;
            float wv = __expf(v);
            srec[j].x = wv;
            sum += wv;
        }
        float inv = 1.f / (sum + 1e-16f);
        for (int j = s0; j < s1; j++)
            srec[j].x *= inv;
    }
    __syncthreads();

    int eh  = lane >> 4;                        // edge parity half
    int ch2 = lane & 15;                        // channel-pair index
    int chOff2 = (ch2 >> 3) * (AGG7_HALF + AGG7_PAD) + (ch2 & 7) * 2;
    float* __restrict__ Hout = ((ch2 < 8) ? H0 : H1) + (ch2 & 7) * 2;

    // Phase B: warp per node; each lane = (edge parity, channel pair)
    for (int n = w; n < NN; n += 32) {
        int s0 = soff[n], s1 = soff[n + 1];
        float ax = 0.f, ay = 0.f;
        int j = s0 + eh;
        for (; j + 2 < s1; j += 4) {
            float2 r0 = srec[j];
            float2 r1 = srec[j + 2];
            const float2 h0 = *(const float2*)&Hs[__float_as_int(r0.y) + chOff2];
            const float2 h1 = *(const float2*)&Hs[__float_as_int(r1.y) + chOff2];
            ax += r0.x * h0.x + r1.x * h1.x;
            ay += r0.x * h0.y + r1.x * h1.y;
        }
        if (j < s1) {
            float2 r0 = srec[j];
            const float2 h0 = *(const float2*)&Hs[__float_as_int(r0.y) + chOff2];
            ax += r0.x * h0.x;
            ay += r0.x * h0.y;
        }
        ax += __shfl_down_sync(0xffffffffu, ax, 16);
        ay += __shfl_down_sync(0xffffffffu, ay, 16);
        if (eh == 0)
            *(float2*)&Hout[n * 16] = make_float2(ax, ay);   // in-place
    }
}

// ---------------- head mean + bias + elu -> X1 (final layer only) ------------
__global__ void k_finish(const float* __restrict__ bg_l) {
    int tid = threadIdx.x;
    int r = blockIdx.x * 4 + (tid >> 6);
    int c = tid & 63;
    float v = 0.f;
#pragma unroll
    for (int h = 0; h < HEADS; h++) {
        int cc = h * 64 + c;
        v += g_H[(size_t)(cc >> 4) * HSLICE + (size_t)r * 16 + (cc & 15)];
    }
    v = 0.25f * v + bg_l[c];
    v = v > 0.f ? v : expm1f(v);
    g_X1[(size_t)r * 64 + c] = v;
}

// ---------------- GI split-K GEMM -------------------------------------------
__global__ void __launch_bounds__(256) k_gi_gemm(const float* __restrict__ Wih) {
    __shared__ float As[64][33];
    __shared__ float Ws[64][33];
    int kBase = blockIdx.x * KCH;
    int gateBase = blockIdx.y * 64;
    int tid = threadIdx.x;
    int tx = tid & 15, ty = tid >> 4;
    float acc[4][4] = {};
    for (int kt = 0; kt < KCH / 32; kt++) {
        int k0 = kBase + kt * 32;
#pragma unroll
        for (int i = 0; i < 8; i++) {
            int idx = tid + i * 256;
            int r = idx >> 5, kk = idx & 31;
            As[r][kk] = g_X1[r * NH + k0 + kk];
            Ws[r][kk] = Wih[(size_t)(gateBase + r) * NH + k0 + kk];
        }
        __syncthreads();
#pragma unroll
        for (int kk = 0; kk < 32; kk++) {
            float a[4], wv[4];
#pragma unroll
            for (int i = 0; i < 4; i++) a[i] = As[ty * 4 + i][kk];
#pragma unroll
            for (int j = 0; j < 4; j++) wv[j] = Ws[tx * 4 + j][kk];
#pragma unroll
            for (int i = 0; i < 4; i++)
#pragma unroll
                for (int j = 0; j < 4; j++)
                    acc[i][j] += a[i] * wv[j];
        }
        __syncthreads();
    }
#pragma unroll
    for (int i = 0; i < 4; i++)
#pragma unroll
        for (int j = 0; j < 4; j++)
            g_GIpart[(blockIdx.x * GG + ty * 4 + i) * GATES + gateBase + tx * 4 + j] = acc[i][j];
}

__global__ void k_gi_reduce(const float* __restrict__ b_ih) {
    int idx = blockIdx.x * blockDim.x + threadIdx.x;
    int j = idx % GATES;
    float s = b_ih[j];
    for (int kc = 0; kc < NCHUNK; kc++)
        s += g_GIpart[kc * GG * GATES + idx];
    g_GI[idx] = s;
}

// ---------------- GRU recurrence ----------------
__global__ void __launch_bounds__(256) k_gru(const float* __restrict__ Whh,
                                             const float* __restrict__ bhh) {
    __shared__ float h[BB][HID];
    __shared__ float gh[BB][GATES];
    int tid = threadIdx.x;
    h[tid >> 6][tid & 63] = 0.f;
    __syncthreads();
    for (int t = 0; t < TT; t++) {
#pragma unroll
        for (int q = 0; q < 3; q++) {
            int idx = tid + q * 256;
            int b = idx / GATES, j = idx % GATES;
            float s = bhh[j];
#pragma unroll
            for (int c = 0; c < HID; c++)
                s += h[b][c] * Whh[j * HID + c];
            gh[b][j] = s;
        }
        __syncthreads();
        int b = tid >> 6, c = tid & 63;
        int g = b * TT + t;
        float ir = g_GI[g * GATES + c]        + gh[b][c];
        float iz = g_GI[g * GATES + 64 + c]   + gh[b][64 + c];
        float in = g_GI[g * GATES + 128 + c];
        float hn = gh[b][128 + c];
        float r = 1.f / (1.f + expf(-ir));
        float z = 1.f / (1.f + expf(-iz));
        float nn = tanhf(in + r * hn);
        float hnew = (1.f - z) * nn + z * h[b][c];
        __syncthreads();
        h[b][c] = hnew;
        __syncthreads();
    }
    g_hT[tid] = h[tid >> 6][tid & 63];
}

// ---------------- final FC ----------------
__global__ void k_fc(const float* __restrict__ Wfc, const float* __restrict__ bfc,
                     float* __restrict__ out) {
    int b = blockIdx.x;
    int n = blockIdx.y * 256 + threadIdx.x;
    if (n >= NN) return;
    float s = bfc[n];
#pragma unroll
    for (int c = 0; c < HID; c++)
        s += g_hT[b * HID + c] * Wfc[c * NN + n];
    out[b * NN + n] = s;
}

// ---------------- launcher ----------------
extern "C" void kernel_launch(void* const* d_in, const int* in_sizes, int n_in,
                              void* d_out, int out_size) {
    const float* x_seq = (const float*)d_in[0];
    const int*   edge_index = (const int*)d_in[1];
    const float* W_in = (const float*)d_in[3];
    const float* b_in = (const float*)d_in[4];
    const float* Wg   = (const float*)d_in[5];
    const float* a_src= (const float*)d_in[6];
    const float* a_dst= (const float*)d_in[7];
    const float* bg   = (const float*)d_in[8];
    const float* W_ih = (const float*)d_in[9];
    const float* W_hh = (const float*)d_in[10];
    const float* b_ih = (const float*)d_in[11];
    const float* b_hh = (const float*)d_in[12];
    const float* W_fc = (const float*)d_in[13];
    const float* b_fc = (const float*)d_in[14];
    float* out = (float*)d_out;

    cudaFuncSetAttribute(k_gat_agg7,
                         cudaFuncAttributeMaxDynamicSharedMemorySize, AGG7_SMEM);

    // launches 1-3; #4 = layer-0 gemm (ncu slot -> verify f32x2)
    k_csr_all<<<1, 1024>>>(edge_index);
    k_input_fc<<<RR / 8, 256>>>(x_seq, W_in, b_in, 0);
    k_input_fc<<<RR / 8, 256>>>(x_seq, W_in, b_in, RR / 2);

    for (int l = 0; l < LL; l++) {
        const float* bgPrev = (l == 0) ? nullptr : (bg + (size_t)(l - 1) * HID);
        k_gat_gemm<<<RR / 64, 256>>>(bgPrev, Wg + (size_t)l * HID * 256,
                                     a_src + (size_t)l * HEADS * HID,
                                     a_dst + (size_t)l * HEADS * HID);
        k_gat_agg7<<<dim3(GG, 8), 1024, AGG7_SMEM>>>();
    }
    // layer-4 aggregated H -> X1 for the GRU input GEMM
    k_finish<<<RR / 4, 256>>>(bg + (size_t)(LL - 1) * HID);

    k_gi_gemm<<<dim3(NCHUNK, 3), 256>>>(W_ih);
    k_gi_reduce<<<(GG * GATES) / 256, 256>>>(b_ih);
    k_gru<<<1, 256>>>(W_hh, b_hh);
    k_fc<<<dim3(BB, 4), 256>>>(W_fc, b_fc, out);
}